// round 1
// baseline (speedup 1.0000x reference)
#include <cuda_runtime.h>
#include <math.h>

#define BB   16
#define LL   512
#define DD   768
#define HH   12
#define KDIM 64
#define FFD  3072
#define NLAY 12
#define NCLS 4
#define NTOK (BB*LL)   // 8192

// ---------------- scratch (device globals; no allocation allowed) ----------------
__device__ float g_h [NTOK*DD];
__device__ float g_q [NTOK*DD];
__device__ float g_k [NTOK*DD];
__device__ float g_v [NTOK*DD];
__device__ float g_o [NTOK*DD];
__device__ float g_t1[(size_t)NTOK*FFD];
__device__ float g_t2[NTOK*DD];
__device__ float g_scores[(size_t)BB*HH*LL*LL];   // 201 MB
__device__ int   g_mixpos[NTOK];
__device__ float g_pooled[BB*DD];

// ---------------- reductions ----------------
__device__ __forceinline__ float warpSum(float v){
  #pragma unroll
  for (int o=16;o;o>>=1) v += __shfl_xor_sync(0xffffffffu, v, o);
  return v;
}
__device__ __forceinline__ float warpMax(float v){
  #pragma unroll
  for (int o=16;o;o>>=1) v = fmaxf(v, __shfl_xor_sync(0xffffffffu, v, o));
  return v;
}
template<int NWARP>
__device__ __forceinline__ float blockSum(float v, float* sh){
  int lane = threadIdx.x & 31, w = threadIdx.x >> 5;
  v = warpSum(v);
  if (lane == 0) sh[w] = v;
  __syncthreads();
  float r = (lane < NWARP) ? sh[lane] : 0.f;
  r = warpSum(r);
  __syncthreads();
  return r;
}
template<int NWARP>
__device__ __forceinline__ float blockMax(float v, float* sh){
  int lane = threadIdx.x & 31, w = threadIdx.x >> 5;
  v = warpMax(v);
  if (lane == 0) sh[w] = v;
  __syncthreads();
  float r = (lane < NWARP) ? sh[lane] : -INFINITY;
  r = warpMax(r);
  __syncthreads();
  return r;
}

// ---------------- generic GEMM: C[M,N] = A[M,K] @ W[K,N] + bias, opt GELU ----------------
// 64x64 tile, BK=16, 256 threads, 4x4 per thread.
template<int ACT>
__global__ void __launch_bounds__(256) gemm64(const float* __restrict__ A,
    const float* __restrict__ W, const float* __restrict__ bias,
    float* __restrict__ C, int M, int N, int K){
  __shared__ float As[16][68];
  __shared__ float Bs[16][68];
  const int m0 = blockIdx.y * 64;
  const int n0 = blockIdx.x * 64;
  const int tid = threadIdx.x;
  const int tr = tid >> 4, tc = tid & 15;
  float acc[4][4] = {};
  for (int k0 = 0; k0 < K; k0 += 16){
    #pragma unroll
    for (int r = 0; r < 4; r++){
      int idx = tid + 256*r;
      int ml = idx >> 4, ka = idx & 15;
      As[ka][ml] = A[(size_t)(m0+ml)*K + (k0+ka)];
      int kb = idx >> 6, nl = idx & 63;
      Bs[kb][nl] = W[(size_t)(k0+kb)*N + (n0+nl)];
    }
    __syncthreads();
    #pragma unroll
    for (int kk = 0; kk < 16; kk++){
      float4 a = *(const float4*)&As[kk][tr*4];
      float4 b = *(const float4*)&Bs[kk][tc*4];
      acc[0][0] += a.x*b.x; acc[0][1] += a.x*b.y; acc[0][2] += a.x*b.z; acc[0][3] += a.x*b.w;
      acc[1][0] += a.y*b.x; acc[1][1] += a.y*b.y; acc[1][2] += a.y*b.z; acc[1][3] += a.y*b.w;
      acc[2][0] += a.z*b.x; acc[2][1] += a.z*b.y; acc[2][2] += a.z*b.z; acc[2][3] += a.z*b.w;
      acc[3][0] += a.w*b.x; acc[3][1] += a.w*b.y; acc[3][2] += a.w*b.z; acc[3][3] += a.w*b.w;
    }
    __syncthreads();
  }
  #pragma unroll
  for (int r = 0; r < 4; r++){
    int m = m0 + tr*4 + r;
    #pragma unroll
    for (int c = 0; c < 4; c++){
      int n = n0 + tc*4 + c;
      float vv = acc[r][c] + bias[n];
      if (ACT == 1) vv = 0.5f*vv*(1.0f + erff(vv*0.70710678118654752440f));
      C[(size_t)m*N + n] = vv;
    }
  }
}

// ---------------- attention scores: S[b,h,i,j] = scale * q[b,i,h,:] . k[kb,j,h,:] ----------------
__global__ void __launch_bounds__(256) attn_scores(const float* __restrict__ q,
    const float* __restrict__ k, const int* __restrict__ mix, float* __restrict__ S){
  const int bh = blockIdx.z, b = bh / HH, h = bh % HH;
  const int kb = mix ? mix[b] : b;
  const int i0 = blockIdx.y*64, j0 = blockIdx.x*64;
  __shared__ float Qs[16][68], Ks[16][68];
  const int tid = threadIdx.x, tr = tid>>4, tc = tid&15;
  float acc[4][4] = {};
  for (int k0=0;k0<KDIM;k0+=16){
    #pragma unroll
    for (int r=0;r<4;r++){
      int idx = tid + 256*r;
      int rl = idx >> 4, kk = idx & 15;
      Qs[kk][rl] = q[(size_t)(b *LL + i0+rl)*DD + h*KDIM + k0+kk];
      Ks[kk][rl] = k[(size_t)(kb*LL + j0+rl)*DD + h*KDIM + k0+kk];
    }
    __syncthreads();
    #pragma unroll
    for (int kk=0;kk<16;kk++){
      float4 a = *(const float4*)&Qs[kk][tr*4];
      float4 b4 = *(const float4*)&Ks[kk][tc*4];
      acc[0][0] += a.x*b4.x; acc[0][1] += a.x*b4.y; acc[0][2] += a.x*b4.z; acc[0][3] += a.x*b4.w;
      acc[1][0] += a.y*b4.x; acc[1][1] += a.y*b4.y; acc[1][2] += a.y*b4.z; acc[1][3] += a.y*b4.w;
      acc[2][0] += a.z*b4.x; acc[2][1] += a.z*b4.y; acc[2][2] += a.z*b4.z; acc[2][3] += a.z*b4.w;
      acc[3][0] += a.w*b4.x; acc[3][1] += a.w*b4.y; acc[3][2] += a.w*b4.z; acc[3][3] += a.w*b4.w;
    }
    __syncthreads();
  }
  float* srow = S + (size_t)bh*LL*LL;
  #pragma unroll
  for (int r=0;r<4;r++){
    int i = i0 + tr*4 + r;
    #pragma unroll
    for (int c=0;c<4;c++){
      int j = j0 + tc*4 + c;
      srow[(size_t)i*LL + j] = acc[r][c]*0.125f;   // 1/sqrt(64)
    }
  }
}

// ---------------- masked softmax over rows of length 512 (exact reference semantics) -------------
__global__ void __launch_bounds__(128) softmax512(float* __restrict__ S,
    const float* __restrict__ amask, const int* __restrict__ mix){
  const int row = blockIdx.x;              // bh*LL + i
  const int bh = row >> 9;
  const int b  = bh / HH;
  const int kb = mix ? mix[b] : b;
  float* sr = S + (size_t)row*LL;
  const float* mr = amask + (size_t)kb*LL;
  __shared__ float red[4];
  float vals[4], ms[4];
  float mx = -INFINITY;
  #pragma unroll
  for (int r=0;r<4;r++){
    int j = threadIdx.x + 128*r;
    float m = mr[j];
    float v = sr[j]*m;
    vals[r]=v; ms[r]=m;
    mx = fmaxf(mx, v);
  }
  mx = blockMax<4>(mx, red);
  float s = 0.f;
  #pragma unroll
  for (int r=0;r<4;r++){
    float e = expf(vals[r]-mx)*ms[r];
    vals[r] = e; s += e;
  }
  s = blockSum<4>(s, red);
  if (s == 0.f) s = 1.f;
  float inv = 1.f/s;
  #pragma unroll
  for (int r=0;r<4;r++) sr[threadIdx.x + 128*r] = vals[r]*inv;
}

// ---------------- O = softmax(S) @ V ----------------
__global__ void __launch_bounds__(256) attn_av(const float* __restrict__ S,
    const float* __restrict__ v, float* __restrict__ o){
  const int bh = blockIdx.y, b = bh/HH, h = bh%HH;
  const int i0 = blockIdx.x*64;
  __shared__ float Ss[16][68], Vs[16][68];
  const int tid=threadIdx.x, tr=tid>>4, tc=tid&15;
  float acc[4][4]={};
  const float* sbase = S + (size_t)bh*LL*LL;
  for (int j0=0;j0<LL;j0+=16){
    #pragma unroll
    for (int r=0;r<4;r++){
      int idx = tid + 256*r;
      int il = idx>>4, jj = idx&15;
      Ss[jj][il] = sbase[(size_t)(i0+il)*LL + j0+jj];
      int j2 = idx>>6, dl = idx&63;
      Vs[j2][dl] = v[(size_t)(b*LL + j0+j2)*DD + h*KDIM + dl];
    }
    __syncthreads();
    #pragma unroll
    for (int kk=0;kk<16;kk++){
      float4 a = *(const float4*)&Ss[kk][tr*4];
      float4 b4 = *(const float4*)&Vs[kk][tc*4];
      acc[0][0] += a.x*b4.x; acc[0][1] += a.x*b4.y; acc[0][2] += a.x*b4.z; acc[0][3] += a.x*b4.w;
      acc[1][0] += a.y*b4.x; acc[1][1] += a.y*b4.y; acc[1][2] += a.y*b4.z; acc[1][3] += a.y*b4.w;
      acc[2][0] += a.z*b4.x; acc[2][1] += a.z*b4.y; acc[2][2] += a.z*b4.z; acc[2][3] += a.z*b4.w;
      acc[3][0] += a.w*b4.x; acc[3][1] += a.w*b4.y; acc[3][2] += a.w*b4.z; acc[3][3] += a.w*b4.w;
    }
    __syncthreads();
  }
  #pragma unroll
  for (int r=0;r<4;r++){
    int i = i0 + tr*4 + r;
    #pragma unroll
    for (int c=0;c<4;c++){
      int d = tc*4 + c;
      o[(size_t)(b*LL + i)*DD + h*KDIM + d] = acc[r][c];
    }
  }
}

// ---------------- cross_sim = max over heads; masked argmax over j (tie -> larger j) ------------
// Positions: i==0 -> 0, i==L-1 -> L-1, else argmax over j in [1, L-2].
__global__ void __launch_bounds__(256) cross_argmax(const float* __restrict__ S,
    int* __restrict__ pos){
  const int i = blockIdx.x, b = blockIdx.y;
  if (i == 0 || i == LL-1){
    if (threadIdx.x == 0) pos[b*LL + i] = i;
    return;
  }
  __shared__ float sval[256];
  __shared__ int   sidx[256];
  float best = -1.f; int bestj = 0;
  for (int j = threadIdx.x; j < LL; j += 256){
    if (j < 1 || j > LL-2) continue;
    float cs = -INFINITY;
    #pragma unroll
    for (int h=0; h<HH; h++)
      cs = fmaxf(cs, S[((size_t)(b*HH+h)*LL + i)*LL + j]);
    if (cs > best || (cs == best && j > bestj)){ best = cs; bestj = j; }
  }
  sval[threadIdx.x]=best; sidx[threadIdx.x]=bestj;
  __syncthreads();
  for (int s=128; s; s>>=1){
    if (threadIdx.x < s){
      float v2 = sval[threadIdx.x+s]; int j2 = sidx[threadIdx.x+s];
      if (v2 > sval[threadIdx.x] || (v2 == sval[threadIdx.x] && j2 > sidx[threadIdx.x])){
        sval[threadIdx.x]=v2; sidx[threadIdx.x]=j2;
      }
    }
    __syncthreads();
  }
  if (threadIdx.x == 0) pos[b*LL + i] = sidx[0];
}

// ---------------- h_out = alpha*h + (1-alpha)*h[mix[b], pos] ----------------
__global__ void __launch_bounds__(256) mixup_apply(const float* __restrict__ h,
    const int* __restrict__ mix, const int* __restrict__ pos,
    const float* __restrict__ alphap, float* __restrict__ outh){
  const int t = blockIdx.x, b = t / LL;
  const float a = *alphap;
  const int mb = mix[b], p = pos[t];
  const float* cur = h + (size_t)t*DD;
  const float* src = h + (size_t)(mb*LL + p)*DD;
  float* dst = outh + (size_t)t*DD;
  for (int d = threadIdx.x; d < DD; d += 256)
    dst[d] = a*cur[d] + (1.f-a)*src[d];
}

__global__ void copyf(const float* __restrict__ s, float* __restrict__ d, int n){
  int i = blockIdx.x*blockDim.x + threadIdx.x;
  if (i < n) d[i] = s[i];
}

// ---------------- embedding + LN ----------------
__global__ void __launch_bounds__(256) embed_ln(const int* __restrict__ ids,
    const float* __restrict__ we, const float* __restrict__ pe, const float* __restrict__ te,
    const float* __restrict__ w, const float* __restrict__ bprm, float* __restrict__ h){
  const int t = blockIdx.x, l = t % LL;
  __shared__ float red[8];
  const int id = ids[t];
  float xs[3]; float s = 0.f;
  #pragma unroll
  for (int r=0;r<3;r++){
    int d = threadIdx.x + 256*r;
    float x = we[(size_t)id*DD + d] + pe[(size_t)l*DD + d] + te[d];
    xs[r]=x; s += x;
  }
  float mu = blockSum<8>(s, red) * (1.f/DD);
  float vs = 0.f;
  #pragma unroll
  for (int r=0;r<3;r++){ float c = xs[r]-mu; vs += c*c; }
  float var = blockSum<8>(vs, red) * (1.f/DD);
  float rstd = rsqrtf(var + 1e-12f);
  #pragma unroll
  for (int r=0;r<3;r++){
    int d = threadIdx.x + 256*r;
    h[(size_t)t*DD + d] = (xs[r]-mu)*rstd*w[d] + bprm[d];
  }
}

// ---------------- h = LN(hin + res) * w + b ----------------
__global__ void __launch_bounds__(256) add_ln(const float* __restrict__ hin,
    const float* __restrict__ res, const float* __restrict__ w,
    const float* __restrict__ bprm, float* __restrict__ hout){
  const int t = blockIdx.x;
  __shared__ float red[8];
  float xs[3]; float s = 0.f;
  #pragma unroll
  for (int r=0;r<3;r++){
    int d = threadIdx.x + 256*r;
    float x = hin[(size_t)t*DD + d] + res[(size_t)t*DD + d];
    xs[r]=x; s += x;
  }
  float mu = blockSum<8>(s, red) * (1.f/DD);
  float vs = 0.f;
  #pragma unroll
  for (int r=0;r<3;r++){ float c = xs[r]-mu; vs += c*c; }
  float var = blockSum<8>(vs, red) * (1.f/DD);
  float rstd = rsqrtf(var + 1e-12f);
  #pragma unroll
  for (int r=0;r<3;r++){
    int d = threadIdx.x + 256*r;
    hout[(size_t)t*DD + d] = (xs[r]-mu)*rstd*w[d] + bprm[d];
  }
}

// ---------------- mean pool over sequence ----------------
__global__ void __launch_bounds__(256) pool_mean(const float* __restrict__ h,
    float* __restrict__ p){
  const int b = blockIdx.x;
  float acc[3] = {0.f,0.f,0.f};
  for (int l=0; l<LL; l++){
    const float* row = h + (size_t)(b*LL + l)*DD;
    #pragma unroll
    for (int r=0;r<3;r++) acc[r] += row[threadIdx.x + 256*r];
  }
  #pragma unroll
  for (int r=0;r<3;r++)
    p[(size_t)b*DD + threadIdx.x + 256*r] = acc[r]*(1.f/LL);
}

// ---------------- classifier head ----------------
__global__ void __launch_bounds__(128) head_kernel(const float* __restrict__ p,
    const float* __restrict__ c1w, const float* __restrict__ c1b,
    const float* __restrict__ c2w, const float* __restrict__ c2b,
    float* __restrict__ out){
  const int b = blockIdx.x;
  __shared__ float ps[DD];
  __shared__ float c1s[128];
  for (int d = threadIdx.x; d < DD; d += 128) ps[d] = p[(size_t)b*DD + d];
  __syncthreads();
  const int t = threadIdx.x;
  float s = c1b[t];
  for (int d = 0; d < DD; d++) s += ps[d]*c1w[(size_t)d*128 + t];
  c1s[t] = tanhf(s);
  __syncthreads();
  if (t < NCLS){
    float o = c2b[t];
    #pragma unroll
    for (int j=0;j<128;j++) o += c1s[j]*c2w[j*NCLS + t];
    out[b*NCLS + t] = o;
  }
}

// ---------------- launcher ----------------
extern "C" void kernel_launch(void* const* d_in, const int* in_sizes, int n_in,
                              void* d_out, int out_size){
  const int*   ids   = (const int*)  d_in[0];
  const float* amask = (const float*)d_in[1];
  const int*   mix   = (const int*)  d_in[2];
  // d_in[3..5] = is_cls/is_sep/is_normal: position-deterministic, unused
  const float* alpha = (const float*)d_in[6];
  const float* we    = (const float*)d_in[7];
  const float* pe    = (const float*)d_in[8];
  const float* te    = (const float*)d_in[9];   // use row 0 only
  const float* elnw  = (const float*)d_in[10];
  const float* elnb  = (const float*)d_in[11];
  const float* Wq = (const float*)d_in[12]; const float* bq = (const float*)d_in[13];
  const float* Wk = (const float*)d_in[14]; const float* bk = (const float*)d_in[15];
  const float* Wv = (const float*)d_in[16]; const float* bv = (const float*)d_in[17];
  const float* Wo = (const float*)d_in[18]; const float* bo = (const float*)d_in[19];
  const float* l1w = (const float*)d_in[20]; const float* l1b = (const float*)d_in[21];
  const float* Wf1 = (const float*)d_in[22]; const float* bf1 = (const float*)d_in[23];
  const float* Wf2 = (const float*)d_in[24]; const float* bf2 = (const float*)d_in[25];
  const float* l2w = (const float*)d_in[26]; const float* l2b = (const float*)d_in[27];
  const float* c1w = (const float*)d_in[28]; const float* c1b = (const float*)d_in[29];
  const float* c2w = (const float*)d_in[30]; const float* c2b = (const float*)d_in[31];
  float* out = (float*)d_out;

  float *h,*q,*k,*v,*o,*t1,*t2,*sc,*pl; int* mpos;
  cudaGetSymbolAddress((void**)&h,    g_h);
  cudaGetSymbolAddress((void**)&q,    g_q);
  cudaGetSymbolAddress((void**)&k,    g_k);
  cudaGetSymbolAddress((void**)&v,    g_v);
  cudaGetSymbolAddress((void**)&o,    g_o);
  cudaGetSymbolAddress((void**)&t1,   g_t1);
  cudaGetSymbolAddress((void**)&t2,   g_t2);
  cudaGetSymbolAddress((void**)&sc,   g_scores);
  cudaGetSymbolAddress((void**)&pl,   g_pooled);
  cudaGetSymbolAddress((void**)&mpos, g_mixpos);

  embed_ln<<<NTOK,256>>>(ids, we, pe, te, elnw, elnb, h);

  for (int layer = 0; layer < NLAY; layer++){
    const float* Wq_l = Wq + (size_t)layer*DD*DD;  const float* bq_l = bq + (size_t)layer*DD;
    const float* Wk_l = Wk + (size_t)layer*DD*DD;  const float* bk_l = bk + (size_t)layer*DD;
    const float* Wv_l = Wv + (size_t)layer*DD*DD;  const float* bv_l = bv + (size_t)layer*DD;
    const float* Wo_l = Wo + (size_t)layer*DD*DD;  const float* bo_l = bo + (size_t)layer*DD;
    const float* Wf1_l = Wf1 + (size_t)layer*DD*FFD; const float* bf1_l = bf1 + (size_t)layer*FFD;
    const float* Wf2_l = Wf2 + (size_t)layer*FFD*DD; const float* bf2_l = bf2 + (size_t)layer*DD;

    if (layer == 0){
      // mixup: q,k from pre-mix h; cross attention against k[mix]
      gemm64<0><<<dim3(DD/64, NTOK/64), 256>>>(h, Wq_l, bq_l, q, NTOK, DD, DD);
      gemm64<0><<<dim3(DD/64, NTOK/64), 256>>>(h, Wk_l, bk_l, k, NTOK, DD, DD);
      attn_scores<<<dim3(LL/64, LL/64, BB*HH), 256>>>(q, k, mix, sc);
      softmax512<<<BB*HH*LL, 128>>>(sc, amask, mix);
      cross_argmax<<<dim3(LL, BB), 256>>>(sc, mpos);
      mixup_apply<<<NTOK, 256>>>(h, mix, mpos, alpha, t2);
      copyf<<<(NTOK*DD + 255)/256, 256>>>(t2, h, NTOK*DD);
    }

    gemm64<0><<<dim3(DD/64, NTOK/64), 256>>>(h, Wq_l, bq_l, q, NTOK, DD, DD);
    gemm64<0><<<dim3(DD/64, NTOK/64), 256>>>(h, Wk_l, bk_l, k, NTOK, DD, DD);
    gemm64<0><<<dim3(DD/64, NTOK/64), 256>>>(h, Wv_l, bv_l, v, NTOK, DD, DD);

    attn_scores<<<dim3(LL/64, LL/64, BB*HH), 256>>>(q, k, nullptr, sc);
    softmax512<<<BB*HH*LL, 128>>>(sc, amask, nullptr);
    attn_av<<<dim3(LL/64, BB*HH), 256>>>(sc, v, o);

    gemm64<0><<<dim3(DD/64, NTOK/64), 256>>>(o, Wo_l, bo_l, t2, NTOK, DD, DD);
    add_ln<<<NTOK, 256>>>(h, t2, l1w + (size_t)layer*DD, l1b + (size_t)layer*DD, h);

    gemm64<1><<<dim3(FFD/64, NTOK/64), 256>>>(h, Wf1_l, bf1_l, t1, NTOK, FFD, DD);
    gemm64<0><<<dim3(DD/64, NTOK/64), 256>>>(t1, Wf2_l, bf2_l, t2, NTOK, DD, FFD);
    add_ln<<<NTOK, 256>>>(h, t2, l2w + (size_t)layer*DD, l2b + (size_t)layer*DD, h);
  }

  pool_mean<<<BB, 256>>>(h, pl);
  head_kernel<<<BB, 128>>>(pl, c1w, c1b, c2w, c2b, out);
}

// round 3
// speedup vs baseline: 1.4146x; 1.4146x over previous
#include <cuda_runtime.h>
#include <math.h>
#include <stdint.h>

#define BB   16
#define LL   512
#define DD   768
#define HH   12
#define KDIM 64
#define FFD  3072
#define NLAY 12
#define NCLS 4
#define NTOK (BB*LL)   // 8192

// ---------------- scratch (device globals; no allocation allowed) ----------------
__device__ float g_h [NTOK*DD];
__device__ float g_q [NTOK*DD];
__device__ float g_k [NTOK*DD];
__device__ float g_v [NTOK*DD];
__device__ float g_o [NTOK*DD];
__device__ float g_t1[(size_t)NTOK*FFD];
__device__ float g_t2[NTOK*DD];
__device__ float g_scores[(size_t)BB*HH*LL*LL];   // 201 MB
__device__ int   g_mixpos[NTOK];
__device__ float g_pooled[BB*DD];

// ======================= 3xTF32 mma.sync GEMM =======================
// C[M,N] = A[M,K] @ W[K,N] + bias (opt exact GELU).
// CTA tile 128x128, BK=32, 256 threads = 8 warps (2m x 4n), warp tile 64x32.
// Each warp: 4 m-tiles (m16) x 4 n-tiles (n8), mma.m16n8k8 tf32, fp32 accum.
// 3xTF32: a = ah + al, b = bh + bl; D += ah*bh + al*bh + ah*bl  (~fp32 accuracy).

__device__ __forceinline__ void splitf(float x, uint32_t& hi, uint32_t& lo){
  uint32_t h;
  asm("cvt.rna.tf32.f32 %0, %1;" : "=r"(h) : "f"(x));
  hi = h;
  float r = x - __uint_as_float(h);
  asm("cvt.rna.tf32.f32 %0, %1;" : "=r"(lo) : "f"(r));
}

__device__ __forceinline__ void mma_tf32(float* d, const uint32_t* a, const uint32_t* b){
  asm volatile(
    "mma.sync.aligned.m16n8k8.row.col.f32.tf32.tf32.f32 "
    "{%0,%1,%2,%3},{%4,%5,%6,%7},{%8,%9},{%0,%1,%2,%3};"
    : "+f"(d[0]), "+f"(d[1]), "+f"(d[2]), "+f"(d[3])
    : "r"(a[0]), "r"(a[1]), "r"(a[2]), "r"(a[3]), "r"(b[0]), "r"(b[1]));
}

#define AS_F 4608           // 128 rows * 36 stride (floats)
#define BS_F 4352           // 32 rows * 136 stride
#define BUF_F (AS_F + BS_F) // 8960 floats per buffer
#define GEMM_SMEM (2*BUF_F*4)

template<int ACT>
__global__ void __launch_bounds__(256) gemm_mma(const float* __restrict__ A,
    const float* __restrict__ W, const float* __restrict__ bias,
    float* __restrict__ C, int M, int N, int K){
  extern __shared__ float sm[];
  const int tid = threadIdx.x, lane = tid & 31, wid = tid >> 5;
  const int wm = wid & 1, wn = wid >> 1;
  const int g = lane >> 2, tig = lane & 3;
  const int m0 = blockIdx.y * 128, n0 = blockIdx.x * 128;

  float acc[4][4][4] = {};

  // prologue: load tile 0 into buffer 0
  #pragma unroll
  for (int i = 0; i < 4; i++){
    int idx = tid + 256*i;
    float4 va = *(const float4*)&A[(size_t)(m0 + (idx>>3))*K + (idx&7)*4];
    *(float4*)&sm[(idx>>3)*36 + (idx&7)*4] = va;
    float4 vb = *(const float4*)&W[(size_t)(idx>>5)*N + n0 + (idx&31)*4];
    *(float4*)&sm[AS_F + (idx>>5)*136 + (idx&31)*4] = vb;
  }
  __syncthreads();

  const int nkt = K >> 5;
  for (int kt = 0; kt < nkt; kt++){
    float4 rA[4], rB[4];
    const bool pf = (kt+1 < nkt);
    if (pf){
      int k0 = (kt+1) << 5;
      #pragma unroll
      for (int i = 0; i < 4; i++){
        int idx = tid + 256*i;
        rA[i] = *(const float4*)&A[(size_t)(m0 + (idx>>3))*K + k0 + (idx&7)*4];
        rB[i] = *(const float4*)&W[(size_t)(k0 + (idx>>5))*N + n0 + (idx&31)*4];
      }
    }
    const float* As = sm + (kt&1)*BUF_F;
    const float* Bs = As + AS_F;

    #pragma unroll
    for (int ks = 0; ks < 4; ks++){
      uint32_t ah[4][4], al[4][4], bh[4][2], bl[4][2];
      #pragma unroll
      for (int mt = 0; mt < 4; mt++){
        int r0 = wm*64 + mt*16 + g;
        int c0 = ks*8 + tig;
        splitf(As[r0*36 + c0],        ah[mt][0], al[mt][0]);
        splitf(As[(r0+8)*36 + c0],    ah[mt][1], al[mt][1]);
        splitf(As[r0*36 + c0+4],      ah[mt][2], al[mt][2]);
        splitf(As[(r0+8)*36 + c0+4],  ah[mt][3], al[mt][3]);
      }
      #pragma unroll
      for (int nt = 0; nt < 4; nt++){
        int cc = wn*32 + nt*8 + g;
        int r0 = ks*8 + tig;
        splitf(Bs[r0*136 + cc],       bh[nt][0], bl[nt][0]);
        splitf(Bs[(r0+4)*136 + cc],   bh[nt][1], bl[nt][1]);
      }
      #pragma unroll
      for (int mt = 0; mt < 4; mt++)
        #pragma unroll
        for (int nt = 0; nt < 4; nt++){
          mma_tf32(acc[mt][nt], ah[mt], bh[nt]);
          mma_tf32(acc[mt][nt], al[mt], bh[nt]);
          mma_tf32(acc[mt][nt], ah[mt], bl[nt]);
        }
    }

    if (pf){
      float* Ad = sm + ((kt+1)&1)*BUF_F;
      float* Bd = Ad + AS_F;
      #pragma unroll
      for (int i = 0; i < 4; i++){
        int idx = tid + 256*i;
        *(float4*)&Ad[(idx>>3)*36 + (idx&7)*4]   = rA[i];
        *(float4*)&Bd[(idx>>5)*136 + (idx&31)*4] = rB[i];
      }
    }
    __syncthreads();
  }

  // epilogue
  #pragma unroll
  for (int mt = 0; mt < 4; mt++){
    int r0 = m0 + wm*64 + mt*16 + g;
    #pragma unroll
    for (int nt = 0; nt < 4; nt++){
      int c = n0 + wn*32 + nt*8 + tig*2;
      float b0 = bias[c], b1 = bias[c+1];
      float2 v0, v1;
      v0.x = acc[mt][nt][0] + b0; v0.y = acc[mt][nt][1] + b1;
      v1.x = acc[mt][nt][2] + b0; v1.y = acc[mt][nt][3] + b1;
      if (ACT == 1){
        v0.x = 0.5f*v0.x*(1.0f + erff(v0.x*0.70710678118654752440f));
        v0.y = 0.5f*v0.y*(1.0f + erff(v0.y*0.70710678118654752440f));
        v1.x = 0.5f*v1.x*(1.0f + erff(v1.x*0.70710678118654752440f));
        v1.y = 0.5f*v1.y*(1.0f + erff(v1.y*0.70710678118654752440f));
      }
      *(float2*)&C[(size_t)r0*N + c]     = v0;
      *(float2*)&C[(size_t)(r0+8)*N + c] = v1;
    }
  }
}

// ---------------- reductions ----------------
__device__ __forceinline__ float warpSum(float v){
  #pragma unroll
  for (int o=16;o;o>>=1) v += __shfl_xor_sync(0xffffffffu, v, o);
  return v;
}
__device__ __forceinline__ float warpMax(float v){
  #pragma unroll
  for (int o=16;o;o>>=1) v = fmaxf(v, __shfl_xor_sync(0xffffffffu, v, o));
  return v;
}
template<int NWARP>
__device__ __forceinline__ float blockSum(float v, float* sh){
  int lane = threadIdx.x & 31, w = threadIdx.x >> 5;
  v = warpSum(v);
  if (lane == 0) sh[w] = v;
  __syncthreads();
  float r = (lane < NWARP) ? sh[lane] : 0.f;
  r = warpSum(r);
  __syncthreads();
  return r;
}
template<int NWARP>
__device__ __forceinline__ float blockMax(float v, float* sh){
  int lane = threadIdx.x & 31, w = threadIdx.x >> 5;
  v = warpMax(v);
  if (lane == 0) sh[w] = v;
  __syncthreads();
  float r = (lane < NWARP) ? sh[lane] : -INFINITY;
  r = warpMax(r);
  __syncthreads();
  return r;
}

// ---------------- attention scores (fp32 SIMT) ----------------
__global__ void __launch_bounds__(256) attn_scores(const float* __restrict__ q,
    const float* __restrict__ k, const int* __restrict__ mix, float* __restrict__ S){
  const int bh = blockIdx.z, b = bh / HH, h = bh % HH;
  const int kb = mix ? mix[b] : b;
  const int i0 = blockIdx.y*64, j0 = blockIdx.x*64;
  __shared__ float Qs[16][68], Ks[16][68];
  const int tid = threadIdx.x, tr = tid>>4, tc = tid&15;
  float acc[4][4] = {};
  for (int k0=0;k0<KDIM;k0+=16){
    #pragma unroll
    for (int r=0;r<4;r++){
      int idx = tid + 256*r;
      int rl = idx >> 4, kk = idx & 15;
      Qs[kk][rl] = q[(size_t)(b *LL + i0+rl)*DD + h*KDIM + k0+kk];
      Ks[kk][rl] = k[(size_t)(kb*LL + j0+rl)*DD + h*KDIM + k0+kk];
    }
    __syncthreads();
    #pragma unroll
    for (int kk=0;kk<16;kk++){
      float4 a = *(const float4*)&Qs[kk][tr*4];
      float4 b4 = *(const float4*)&Ks[kk][tc*4];
      acc[0][0] += a.x*b4.x; acc[0][1] += a.x*b4.y; acc[0][2] += a.x*b4.z; acc[0][3] += a.x*b4.w;
      acc[1][0] += a.y*b4.x; acc[1][1] += a.y*b4.y; acc[1][2] += a.y*b4.z; acc[1][3] += a.y*b4.w;
      acc[2][0] += a.z*b4.x; acc[2][1] += a.z*b4.y; acc[2][2] += a.z*b4.z; acc[2][3] += a.z*b4.w;
      acc[3][0] += a.w*b4.x; acc[3][1] += a.w*b4.y; acc[3][2] += a.w*b4.z; acc[3][3] += a.w*b4.w;
    }
    __syncthreads();
  }
  float* srow = S + (size_t)bh*LL*LL;
  #pragma unroll
  for (int r=0;r<4;r++){
    int i = i0 + tr*4 + r;
    #pragma unroll
    for (int c=0;c<4;c++){
      int j = j0 + tc*4 + c;
      srow[(size_t)i*LL + j] = acc[r][c]*0.125f;
    }
  }
}

// ---------------- masked softmax (exact reference semantics) ----------------
__global__ void __launch_bounds__(128) softmax512(float* __restrict__ S,
    const float* __restrict__ amask, const int* __restrict__ mix){
  const int row = blockIdx.x;
  const int bh = row >> 9;
  const int b  = bh / HH;
  const int kb = mix ? mix[b] : b;
  float* sr = S + (size_t)row*LL;
  const float* mr = amask + (size_t)kb*LL;
  __shared__ float red[4];
  float vals[4], ms[4];
  float mx = -INFINITY;
  #pragma unroll
  for (int r=0;r<4;r++){
    int j = threadIdx.x + 128*r;
    float m = mr[j];
    float v = sr[j]*m;
    vals[r]=v; ms[r]=m;
    mx = fmaxf(mx, v);
  }
  mx = blockMax<4>(mx, red);
  float s = 0.f;
  #pragma unroll
  for (int r=0;r<4;r++){
    float e = expf(vals[r]-mx)*ms[r];
    vals[r] = e; s += e;
  }
  s = blockSum<4>(s, red);
  if (s == 0.f) s = 1.f;
  float inv = 1.f/s;
  #pragma unroll
  for (int r=0;r<4;r++) sr[threadIdx.x + 128*r] = vals[r]*inv;
}

// ---------------- O = softmax(S) @ V ----------------
__global__ void __launch_bounds__(256) attn_av(const float* __restrict__ S,
    const float* __restrict__ v, float* __restrict__ o){
  const int bh = blockIdx.y, b = bh/HH, h = bh%HH;
  const int i0 = blockIdx.x*64;
  __shared__ float Ss[16][68], Vs[16][68];
  const int tid=threadIdx.x, tr=tid>>4, tc=tid&15;
  float acc[4][4]={};
  const float* sbase = S + (size_t)bh*LL*LL;
  for (int j0=0;j0<LL;j0+=16){
    #pragma unroll
    for (int r=0;r<4;r++){
      int idx = tid + 256*r;
      int il = idx>>4, jj = idx&15;
      Ss[jj][il] = sbase[(size_t)(i0+il)*LL + j0+jj];
      int j2 = idx>>6, dl = idx&63;
      Vs[j2][dl] = v[(size_t)(b*LL + j0+j2)*DD + h*KDIM + dl];
    }
    __syncthreads();
    #pragma unroll
    for (int kk=0;kk<16;kk++){
      float4 a = *(const float4*)&Ss[kk][tr*4];
      float4 b4 = *(const float4*)&Vs[kk][tc*4];
      acc[0][0] += a.x*b4.x; acc[0][1] += a.x*b4.y; acc[0][2] += a.x*b4.z; acc[0][3] += a.x*b4.w;
      acc[1][0] += a.y*b4.x; acc[1][1] += a.y*b4.y; acc[1][2] += a.y*b4.z; acc[1][3] += a.y*b4.w;
      acc[2][0] += a.z*b4.x; acc[2][1] += a.z*b4.y; acc[2][2] += a.z*b4.z; acc[2][3] += a.z*b4.w;
      acc[3][0] += a.w*b4.x; acc[3][1] += a.w*b4.y; acc[3][2] += a.w*b4.z; acc[3][3] += a.w*b4.w;
    }
    __syncthreads();
  }
  #pragma unroll
  for (int r=0;r<4;r++){
    int i = i0 + tr*4 + r;
    #pragma unroll
    for (int c=0;c<4;c++){
      int d = tc*4 + c;
      o[(size_t)(b*LL + i)*DD + h*KDIM + d] = acc[r][c];
    }
  }
}

// ---------------- cross-sim argmax ----------------
__global__ void __launch_bounds__(256) cross_argmax(const float* __restrict__ S,
    int* __restrict__ pos){
  const int i = blockIdx.x, b = blockIdx.y;
  if (i == 0 || i == LL-1){
    if (threadIdx.x == 0) pos[b*LL + i] = i;
    return;
  }
  __shared__ float sval[256];
  __shared__ int   sidx[256];
  float best = -1.f; int bestj = 0;
  for (int j = threadIdx.x; j < LL; j += 256){
    if (j < 1 || j > LL-2) continue;
    float cs = -INFINITY;
    #pragma unroll
    for (int h=0; h<HH; h++)
      cs = fmaxf(cs, S[((size_t)(b*HH+h)*LL + i)*LL + j]);
    if (cs > best || (cs == best && j > bestj)){ best = cs; bestj = j; }
  }
  sval[threadIdx.x]=best; sidx[threadIdx.x]=bestj;
  __syncthreads();
  for (int s=128; s; s>>=1){
    if (threadIdx.x < s){
      float v2 = sval[threadIdx.x+s]; int j2 = sidx[threadIdx.x+s];
      if (v2 > sval[threadIdx.x] || (v2 == sval[threadIdx.x] && j2 > sidx[threadIdx.x])){
        sval[threadIdx.x]=v2; sidx[threadIdx.x]=j2;
      }
    }
    __syncthreads();
  }
  if (threadIdx.x == 0) pos[b*LL + i] = sidx[0];
}

// ---------------- mixup apply ----------------
__global__ void __launch_bounds__(256) mixup_apply(const float* __restrict__ h,
    const int* __restrict__ mix, const int* __restrict__ pos,
    const float* __restrict__ alphap, float* __restrict__ outh){
  const int t = blockIdx.x, b = t / LL;
  const float a = *alphap;
  const int mb = mix[b], p = pos[t];
  const float* cur = h + (size_t)t*DD;
  const float* src = h + (size_t)(mb*LL + p)*DD;
  float* dst = outh + (size_t)t*DD;
  for (int d = threadIdx.x; d < DD; d += 256)
    dst[d] = a*cur[d] + (1.f-a)*src[d];
}

__global__ void copyf(const float* __restrict__ s, float* __restrict__ d, int n){
  int i = blockIdx.x*blockDim.x + threadIdx.x;
  if (i < n) d[i] = s[i];
}

// ---------------- embedding + LN ----------------
__global__ void __launch_bounds__(256) embed_ln(const int* __restrict__ ids,
    const float* __restrict__ we, const float* __restrict__ pe, const float* __restrict__ te,
    const float* __restrict__ w, const float* __restrict__ bprm, float* __restrict__ h){
  const int t = blockIdx.x, l = t % LL;
  __shared__ float red[8];
  const int id = ids[t];
  float xs[3]; float s = 0.f;
  #pragma unroll
  for (int r=0;r<3;r++){
    int d = threadIdx.x + 256*r;
    float x = we[(size_t)id*DD + d] + pe[(size_t)l*DD + d] + te[d];
    xs[r]=x; s += x;
  }
  float mu = blockSum<8>(s, red) * (1.f/DD);
  float vs = 0.f;
  #pragma unroll
  for (int r=0;r<3;r++){ float c = xs[r]-mu; vs += c*c; }
  float var = blockSum<8>(vs, red) * (1.f/DD);
  float rstd = rsqrtf(var + 1e-12f);
  #pragma unroll
  for (int r=0;r<3;r++){
    int d = threadIdx.x + 256*r;
    h[(size_t)t*DD + d] = (xs[r]-mu)*rstd*w[d] + bprm[d];
  }
}

// ---------------- h = LN(hin + res) ----------------
__global__ void __launch_bounds__(256) add_ln(const float* __restrict__ hin,
    const float* __restrict__ res, const float* __restrict__ w,
    const float* __restrict__ bprm, float* __restrict__ hout){
  const int t = blockIdx.x;
  __shared__ float red[8];
  float xs[3]; float s = 0.f;
  #pragma unroll
  for (int r=0;r<3;r++){
    int d = threadIdx.x + 256*r;
    float x = hin[(size_t)t*DD + d] + res[(size_t)t*DD + d];
    xs[r]=x; s += x;
  }
  float mu = blockSum<8>(s, red) * (1.f/DD);
  float vs = 0.f;
  #pragma unroll
  for (int r=0;r<3;r++){ float c = xs[r]-mu; vs += c*c; }
  float var = blockSum<8>(vs, red) * (1.f/DD);
  float rstd = rsqrtf(var + 1e-12f);
  #pragma unroll
  for (int r=0;r<3;r++){
    int d = threadIdx.x + 256*r;
    hout[(size_t)t*DD + d] = (xs[r]-mu)*rstd*w[d] + bprm[d];
  }
}

// ---------------- mean pool ----------------
__global__ void __launch_bounds__(256) pool_mean(const float* __restrict__ h,
    float* __restrict__ p){
  const int b = blockIdx.x;
  float acc[3] = {0.f,0.f,0.f};
  for (int l=0; l<LL; l++){
    const float* row = h + (size_t)(b*LL + l)*DD;
    #pragma unroll
    for (int r=0;r<3;r++) acc[r] += row[threadIdx.x + 256*r];
  }
  #pragma unroll
  for (int r=0;r<3;r++)
    p[(size_t)b*DD + threadIdx.x + 256*r] = acc[r]*(1.f/LL);
}

// ---------------- classifier head ----------------
__global__ void __launch_bounds__(128) head_kernel(const float* __restrict__ p,
    const float* __restrict__ c1w, const float* __restrict__ c1b,
    const float* __restrict__ c2w, const float* __restrict__ c2b,
    float* __restrict__ out){
  const int b = blockIdx.x;
  __shared__ float ps[DD];
  __shared__ float c1s[128];
  for (int d = threadIdx.x; d < DD; d += 128) ps[d] = p[(size_t)b*DD + d];
  __syncthreads();
  const int t = threadIdx.x;
  float s = c1b[t];
  for (int d = 0; d < DD; d++) s += ps[d]*c1w[(size_t)d*128 + t];
  c1s[t] = tanhf(s);
  __syncthreads();
  if (t < NCLS){
    float o = c2b[t];
    #pragma unroll
    for (int j=0;j<128;j++) o += c1s[j]*c2w[j*NCLS + t];
    out[b*NCLS + t] = o;
  }
}

// ---------------- launcher ----------------
static void launch_gemm(int act, const float* A, const float* W, const float* bias,
                        float* C, int M, int N, int K){
  dim3 grid(N/128, M/128);
  if (act == 1){
    static int set1 = 0;
    if (!set1){ cudaFuncSetAttribute(gemm_mma<1>, cudaFuncAttributeMaxDynamicSharedMemorySize, GEMM_SMEM); set1 = 1; }
    gemm_mma<1><<<grid, 256, GEMM_SMEM>>>(A, W, bias, C, M, N, K);
  } else {
    static int set0 = 0;
    if (!set0){ cudaFuncSetAttribute(gemm_mma<0>, cudaFuncAttributeMaxDynamicSharedMemorySize, GEMM_SMEM); set0 = 1; }
    gemm_mma<0><<<grid, 256, GEMM_SMEM>>>(A, W, bias, C, M, N, K);
  }
}

extern "C" void kernel_launch(void* const* d_in, const int* in_sizes, int n_in,
                              void* d_out, int out_size){
  const int*   ids   = (const int*)  d_in[0];
  const float* amask = (const float*)d_in[1];
  const int*   mix   = (const int*)  d_in[2];
  const float* alpha = (const float*)d_in[6];
  const float* we    = (const float*)d_in[7];
  const float* pe    = (const float*)d_in[8];
  const float* te    = (const float*)d_in[9];
  const float* elnw  = (const float*)d_in[10];
  const float* elnb  = (const float*)d_in[11];
  const float* Wq = (const float*)d_in[12]; const float* bq = (const float*)d_in[13];
  const float* Wk = (const float*)d_in[14]; const float* bk = (const float*)d_in[15];
  const float* Wv = (const float*)d_in[16]; const float* bv = (const float*)d_in[17];
  const float* Wo = (const float*)d_in[18]; const float* bo = (const float*)d_in[19];
  const float* l1w = (const float*)d_in[20]; const float* l1b = (const float*)d_in[21];
  const float* Wf1 = (const float*)d_in[22]; const float* bf1 = (const float*)d_in[23];
  const float* Wf2 = (const float*)d_in[24]; const float* bf2 = (const float*)d_in[25];
  const float* l2w = (const float*)d_in[26]; const float* l2b = (const float*)d_in[27];
  const float* c1w = (const float*)d_in[28]; const float* c1b = (const float*)d_in[29];
  const float* c2w = (const float*)d_in[30]; const float* c2b = (const float*)d_in[31];
  float* out = (float*)d_out;

  float *h,*q,*k,*v,*o,*t1,*t2,*sc,*pl; int* mpos;
  cudaGetSymbolAddress((void**)&h,    g_h);
  cudaGetSymbolAddress((void**)&q,    g_q);
  cudaGetSymbolAddress((void**)&k,    g_k);
  cudaGetSymbolAddress((void**)&v,    g_v);
  cudaGetSymbolAddress((void**)&o,    g_o);
  cudaGetSymbolAddress((void**)&t1,   g_t1);
  cudaGetSymbolAddress((void**)&t2,   g_t2);
  cudaGetSymbolAddress((void**)&sc,   g_scores);
  cudaGetSymbolAddress((void**)&pl,   g_pooled);
  cudaGetSymbolAddress((void**)&mpos, g_mixpos);

  embed_ln<<<NTOK,256>>>(ids, we, pe, te, elnw, elnb, h);

  for (int layer = 0; layer < NLAY; layer++){
    const float* Wq_l = Wq + (size_t)layer*DD*DD;  const float* bq_l = bq + (size_t)layer*DD;
    const float* Wk_l = Wk + (size_t)layer*DD*DD;  const float* bk_l = bk + (size_t)layer*DD;
    const float* Wv_l = Wv + (size_t)layer*DD*DD;  const float* bv_l = bv + (size_t)layer*DD;
    const float* Wo_l = Wo + (size_t)layer*DD*DD;  const float* bo_l = bo + (size_t)layer*DD;
    const float* Wf1_l = Wf1 + (size_t)layer*DD*FFD; const float* bf1_l = bf1 + (size_t)layer*FFD;
    const float* Wf2_l = Wf2 + (size_t)layer*FFD*DD; const float* bf2_l = bf2 + (size_t)layer*DD;

    if (layer == 0){
      launch_gemm(0, h, Wq_l, bq_l, q, NTOK, DD, DD);
      launch_gemm(0, h, Wk_l, bk_l, k, NTOK, DD, DD);
      attn_scores<<<dim3(LL/64, LL/64, BB*HH), 256>>>(q, k, mix, sc);
      softmax512<<<BB*HH*LL, 128>>>(sc, amask, mix);
      cross_argmax<<<dim3(LL, BB), 256>>>(sc, mpos);
      mixup_apply<<<NTOK, 256>>>(h, mix, mpos, alpha, t2);
      copyf<<<(NTOK*DD + 255)/256, 256>>>(t2, h, NTOK*DD);
    }

    launch_gemm(0, h, Wq_l, bq_l, q, NTOK, DD, DD);
    launch_gemm(0, h, Wk_l, bk_l, k, NTOK, DD, DD);
    launch_gemm(0, h, Wv_l, bv_l, v, NTOK, DD, DD);

    attn_scores<<<dim3(LL/64, LL/64, BB*HH), 256>>>(q, k, nullptr, sc);
    softmax512<<<BB*HH*LL, 128>>>(sc, amask, nullptr);
    attn_av<<<dim3(LL/64, BB*HH), 256>>>(sc, v, o);

    launch_gemm(0, o, Wo_l, bo_l, t2, NTOK, DD, DD);
    add_ln<<<NTOK, 256>>>(h, t2, l1w + (size_t)layer*DD, l1b + (size_t)layer*DD, h);

    launch_gemm(1, h, Wf1_l, bf1_l, t1, NTOK, FFD, DD);
    launch_gemm(0, t1, Wf2_l, bf2_l, t2, NTOK, DD, FFD);
    add_ln<<<NTOK, 256>>>(h, t2, l2w + (size_t)layer*DD, l2b + (size_t)layer*DD, h);
  }

  pool_mean<<<BB, 256>>>(h, pl);
  head_kernel<<<BB, 128>>>(pl, c1w, c1b, c2w, c2b, out);
}

// round 4
// speedup vs baseline: 2.1746x; 1.5372x over previous
#include <cuda_runtime.h>
#include <cuda_fp16.h>
#include <math.h>
#include <stdint.h>

#define BB   16
#define LL   512
#define DD   768
#define HH   12
#define KDIM 64
#define FFD  3072
#define NLAY 12
#define NCLS 4
#define NTOK (BB*LL)   // 8192

// ---------------- scratch (device globals; no allocation allowed) ----------------
__device__ float g_h [NTOK*DD];
__device__ float g_q [NTOK*DD];
__device__ float g_k [NTOK*DD];
__device__ float g_v [NTOK*DD];
__device__ float g_o [NTOK*DD];
__device__ float g_t1[(size_t)NTOK*FFD];
__device__ float g_t2[NTOK*DD];
__device__ float g_scores[(size_t)BB*HH*LL*LL];   // 201 MB
__device__ int   g_mixpos[NTOK];
__device__ float g_pooled[BB*DD];

// ======================= fp16 3-term split GEMM (mma.m16n8k16) =======================
// C[M,N] = A[M,K] @ W[K,N] + bias (opt exact GELU).
// a = ah + al/4096, b = bh + bl/4096 (al,bl stored pre-scaled by 4096 to stay fp16-normal).
// acc  += ah*bh ;  acc2 += al*bh + ah*bl ;  C = acc + acc2/4096.
// CTA tile 128x128, BK=32, 256 threads = 8 warps (2m x 4n), warp tile 64x32.
// SMEM: pre-split half tiles; A[m][k] stride 40 halfs, B[k][n] stride 136 halfs.

#define AROW 40
#define BROW 136
#define OFF_AH 0
#define OFF_AL (128*AROW)                   // 5120 halfs
#define OFF_BH (2*128*AROW)                 // 10240
#define OFF_BL (2*128*AROW + 32*BROW)       // 14592
#define BUF_H  (2*128*AROW + 2*32*BROW)     // 18944 halfs
#define GEMM_SMEM (2*BUF_H*2)               // 75776 bytes

__device__ __forceinline__ uint32_t smem_u32(const void* p){
  uint32_t a;
  asm("{ .reg .u64 t; cvta.to.shared.u64 t, %1; cvt.u32.u64 %0, t; }" : "=r"(a) : "l"(p));
  return a;
}

__device__ __forceinline__ void mma_f16(float* d, const uint32_t* a, const uint32_t* b){
  asm volatile(
    "mma.sync.aligned.m16n8k16.row.col.f32.f16.f16.f32 "
    "{%0,%1,%2,%3},{%4,%5,%6,%7},{%8,%9},{%0,%1,%2,%3};"
    : "+f"(d[0]), "+f"(d[1]), "+f"(d[2]), "+f"(d[3])
    : "r"(a[0]), "r"(a[1]), "r"(a[2]), "r"(a[3]), "r"(b[0]), "r"(b[1]));
}

__device__ __forceinline__ void ldmat4(uint32_t* r, uint32_t addr){
  asm volatile("ldmatrix.sync.aligned.m8n8.x4.shared.b16 {%0,%1,%2,%3}, [%4];"
    : "=r"(r[0]), "=r"(r[1]), "=r"(r[2]), "=r"(r[3]) : "r"(addr));
}
__device__ __forceinline__ void ldmat4t(uint32_t* r, uint32_t addr){
  asm volatile("ldmatrix.sync.aligned.m8n8.x4.trans.shared.b16 {%0,%1,%2,%3}, [%4];"
    : "=r"(r[0]), "=r"(r[1]), "=r"(r[2]), "=r"(r[3]) : "r"(addr));
}

// split x into fp16 hi + (scaled) fp16 lo
__device__ __forceinline__ void split2(float x, __half& h, __half& l){
  h = __float2half_rn(x);
  l = __float2half_rn((x - __half2float(h)) * 4096.0f);
}

template<int ACT>
__global__ void __launch_bounds__(256) gemm_f16x3(const float* __restrict__ A,
    const float* __restrict__ W, const float* __restrict__ bias,
    float* __restrict__ C, int M, int N, int K){
  extern __shared__ __half smh[];
  const uint32_t smb = smem_u32(smh);
  const int tid = threadIdx.x, lane = tid & 31, wid = tid >> 5;
  const int wm = wid & 1, wn = wid >> 1;
  const int g = lane >> 2, tig = lane & 3;
  const int m0 = blockIdx.y * 128, n0 = blockIdx.x * 128;

  float acc [4][4][4] = {};
  float acc2[4][4][4] = {};

  // per-lane ldmatrix address components
  const int a_row  = wm*64 + (lane & 7) + ((lane >> 3) & 1) * 8;  // + mt*16
  const int a_koff = (lane & 16) ? 8 : 0;                          // + ks*16
  const int b_row  = (lane & 7) + ((lane >> 3) & 1) * 8;           // + ks*16
  const int b_noff = wn*32 + ((lane & 16) ? 8 : 0);                // + ntp*16

  // stage tile 0
  {
    #pragma unroll
    for (int i = 0; i < 4; i++){
      int idx = tid + 256*i;
      { int r = idx >> 3, kc = (idx & 7) * 4;
        float4 v = *(const float4*)&A[(size_t)(m0 + r)*K + kc];
        __half hx,lx,hy,ly,hz,lz,hw,lw;
        split2(v.x,hx,lx); split2(v.y,hy,ly); split2(v.z,hz,lz); split2(v.w,hw,lw);
        int hb = r*AROW + kc;
        *(__half2*)&smh[OFF_AH + hb]     = __halves2half2(hx,hy);
        *(__half2*)&smh[OFF_AH + hb + 2] = __halves2half2(hz,hw);
        *(__half2*)&smh[OFF_AL + hb]     = __halves2half2(lx,ly);
        *(__half2*)&smh[OFF_AL + hb + 2] = __halves2half2(lz,lw);
      }
      { int kk = idx >> 5, nc = (idx & 31) * 4;
        float4 v = *(const float4*)&W[(size_t)kk*N + n0 + nc];
        __half hx,lx,hy,ly,hz,lz,hw,lw;
        split2(v.x,hx,lx); split2(v.y,hy,ly); split2(v.z,hz,lz); split2(v.w,hw,lw);
        int hb = kk*BROW + nc;
        *(__half2*)&smh[OFF_BH + hb]     = __halves2half2(hx,hy);
        *(__half2*)&smh[OFF_BH + hb + 2] = __halves2half2(hz,hw);
        *(__half2*)&smh[OFF_BL + hb]     = __halves2half2(lx,ly);
        *(__half2*)&smh[OFF_BL + hb + 2] = __halves2half2(lz,lw);
      }
    }
  }
  __syncthreads();

  const int nkt = K >> 5;
  for (int kt = 0; kt < nkt; kt++){
    float4 rA[4], rB[4];
    const bool pf = (kt + 1 < nkt);
    if (pf){
      int k0 = (kt + 1) << 5;
      #pragma unroll
      for (int i = 0; i < 4; i++){
        int idx = tid + 256*i;
        rA[i] = *(const float4*)&A[(size_t)(m0 + (idx>>3))*K + k0 + (idx&7)*4];
        rB[i] = *(const float4*)&W[(size_t)(k0 + (idx>>5))*N + n0 + (idx&31)*4];
      }
    }
    const uint32_t bufb = smb + (uint32_t)(kt & 1) * (BUF_H * 2);

    #pragma unroll
    for (int ks = 0; ks < 2; ks++){
      uint32_t ah[4][4], al[4][4], bh[4][2], bl[4][2];
      #pragma unroll
      for (int mt = 0; mt < 4; mt++){
        uint32_t ad = bufb + (uint32_t)((a_row + mt*16)*AROW + ks*16 + a_koff) * 2;
        ldmat4(ah[mt], ad + OFF_AH*2);
        ldmat4(al[mt], ad + OFF_AL*2);
      }
      #pragma unroll
      for (int ntp = 0; ntp < 2; ntp++){
        uint32_t bd = bufb + (uint32_t)((b_row + ks*16)*BROW + b_noff + ntp*16) * 2;
        uint32_t th[4], tl[4];
        ldmat4t(th, bd + OFF_BH*2);
        ldmat4t(tl, bd + OFF_BL*2);
        bh[ntp*2][0]   = th[0]; bh[ntp*2][1]   = th[1];
        bh[ntp*2+1][0] = th[2]; bh[ntp*2+1][1] = th[3];
        bl[ntp*2][0]   = tl[0]; bl[ntp*2][1]   = tl[1];
        bl[ntp*2+1][0] = tl[2]; bl[ntp*2+1][1] = tl[3];
      }
      #pragma unroll
      for (int mt = 0; mt < 4; mt++)
        #pragma unroll
        for (int nt = 0; nt < 4; nt++){
          mma_f16(acc [mt][nt], ah[mt], bh[nt]);
          mma_f16(acc2[mt][nt], al[mt], bh[nt]);
          mma_f16(acc2[mt][nt], ah[mt], bl[nt]);
        }
    }

    if (pf){
      __half* dst = smh + ((kt + 1) & 1) * BUF_H;
      #pragma unroll
      for (int i = 0; i < 4; i++){
        int idx = tid + 256*i;
        { int r = idx >> 3, kc = (idx & 7) * 4;
          __half hx,lx,hy,ly,hz,lz,hw,lw;
          split2(rA[i].x,hx,lx); split2(rA[i].y,hy,ly); split2(rA[i].z,hz,lz); split2(rA[i].w,hw,lw);
          int hb = r*AROW + kc;
          *(__half2*)&dst[OFF_AH + hb]     = __halves2half2(hx,hy);
          *(__half2*)&dst[OFF_AH + hb + 2] = __halves2half2(hz,hw);
          *(__half2*)&dst[OFF_AL + hb]     = __halves2half2(lx,ly);
          *(__half2*)&dst[OFF_AL + hb + 2] = __halves2half2(lz,lw);
        }
        { int kk = idx >> 5, nc = (idx & 31) * 4;
          __half hx,lx,hy,ly,hz,lz,hw,lw;
          split2(rB[i].x,hx,lx); split2(rB[i].y,hy,ly); split2(rB[i].z,hz,lz); split2(rB[i].w,hw,lw);
          int hb = kk*BROW + nc;
          *(__half2*)&dst[OFF_BH + hb]     = __halves2half2(hx,hy);
          *(__half2*)&dst[OFF_BH + hb + 2] = __halves2half2(hz,hw);
          *(__half2*)&dst[OFF_BL + hb]     = __halves2half2(lx,ly);
          *(__half2*)&dst[OFF_BL + hb + 2] = __halves2half2(lz,lw);
        }
      }
    }
    __syncthreads();
  }

  // epilogue: acc + acc2/4096 + bias (+GELU)
  const float SCL = 1.0f / 4096.0f;
  #pragma unroll
  for (int mt = 0; mt < 4; mt++){
    int r0 = m0 + wm*64 + mt*16 + g;
    #pragma unroll
    for (int nt = 0; nt < 4; nt++){
      int c = n0 + wn*32 + nt*8 + tig*2;
      float b0 = bias[c], b1 = bias[c+1];
      float2 v0, v1;
      v0.x = acc[mt][nt][0] + SCL*acc2[mt][nt][0] + b0;
      v0.y = acc[mt][nt][1] + SCL*acc2[mt][nt][1] + b1;
      v1.x = acc[mt][nt][2] + SCL*acc2[mt][nt][2] + b0;
      v1.y = acc[mt][nt][3] + SCL*acc2[mt][nt][3] + b1;
      if (ACT == 1){
        v0.x = 0.5f*v0.x*(1.0f + erff(v0.x*0.70710678118654752440f));
        v0.y = 0.5f*v0.y*(1.0f + erff(v0.y*0.70710678118654752440f));
        v1.x = 0.5f*v1.x*(1.0f + erff(v1.x*0.70710678118654752440f));
        v1.y = 0.5f*v1.y*(1.0f + erff(v1.y*0.70710678118654752440f));
      }
      *(float2*)&C[(size_t)r0*N + c]     = v0;
      *(float2*)&C[(size_t)(r0+8)*N + c] = v1;
    }
  }
}

// ---------------- reductions ----------------
__device__ __forceinline__ float warpSum(float v){
  #pragma unroll
  for (int o=16;o;o>>=1) v += __shfl_xor_sync(0xffffffffu, v, o);
  return v;
}
__device__ __forceinline__ float warpMax(float v){
  #pragma unroll
  for (int o=16;o;o>>=1) v = fmaxf(v, __shfl_xor_sync(0xffffffffu, v, o));
  return v;
}
template<int NWARP>
__device__ __forceinline__ float blockSum(float v, float* sh){
  int lane = threadIdx.x & 31, w = threadIdx.x >> 5;
  v = warpSum(v);
  if (lane == 0) sh[w] = v;
  __syncthreads();
  float r = (lane < NWARP) ? sh[lane] : 0.f;
  r = warpSum(r);
  __syncthreads();
  return r;
}
template<int NWARP>
__device__ __forceinline__ float blockMax(float v, float* sh){
  int lane = threadIdx.x & 31, w = threadIdx.x >> 5;
  v = warpMax(v);
  if (lane == 0) sh[w] = v;
  __syncthreads();
  float r = (lane < NWARP) ? sh[lane] : -INFINITY;
  r = warpMax(r);
  __syncthreads();
  return r;
}

// ---------------- attention scores (fp32 SIMT) ----------------
__global__ void __launch_bounds__(256) attn_scores(const float* __restrict__ q,
    const float* __restrict__ k, const int* __restrict__ mix, float* __restrict__ S){
  const int bh = blockIdx.z, b = bh / HH, h = bh % HH;
  const int kb = mix ? mix[b] : b;
  const int i0 = blockIdx.y*64, j0 = blockIdx.x*64;
  __shared__ float Qs[16][68], Ks[16][68];
  const int tid = threadIdx.x, tr = tid>>4, tc = tid&15;
  float acc[4][4] = {};
  for (int k0=0;k0<KDIM;k0+=16){
    #pragma unroll
    for (int r=0;r<4;r++){
      int idx = tid + 256*r;
      int rl = idx >> 4, kk = idx & 15;
      Qs[kk][rl] = q[(size_t)(b *LL + i0+rl)*DD + h*KDIM + k0+kk];
      Ks[kk][rl] = k[(size_t)(kb*LL + j0+rl)*DD + h*KDIM + k0+kk];
    }
    __syncthreads();
    #pragma unroll
    for (int kk=0;kk<16;kk++){
      float4 a = *(const float4*)&Qs[kk][tr*4];
      float4 b4 = *(const float4*)&Ks[kk][tc*4];
      acc[0][0] += a.x*b4.x; acc[0][1] += a.x*b4.y; acc[0][2] += a.x*b4.z; acc[0][3] += a.x*b4.w;
      acc[1][0] += a.y*b4.x; acc[1][1] += a.y*b4.y; acc[1][2] += a.y*b4.z; acc[1][3] += a.y*b4.w;
      acc[2][0] += a.z*b4.x; acc[2][1] += a.z*b4.y; acc[2][2] += a.z*b4.z; acc[2][3] += a.z*b4.w;
      acc[3][0] += a.w*b4.x; acc[3][1] += a.w*b4.y; acc[3][2] += a.w*b4.z; acc[3][3] += a.w*b4.w;
    }
    __syncthreads();
  }
  float* srow = S + (size_t)bh*LL*LL;
  #pragma unroll
  for (int r=0;r<4;r++){
    int i = i0 + tr*4 + r;
    #pragma unroll
    for (int c=0;c<4;c++){
      int j = j0 + tc*4 + c;
      srow[(size_t)i*LL + j] = acc[r][c]*0.125f;
    }
  }
}

// ---------------- masked softmax (exact reference semantics) ----------------
__global__ void __launch_bounds__(128) softmax512(float* __restrict__ S,
    const float* __restrict__ amask, const int* __restrict__ mix){
  const int row = blockIdx.x;
  const int bh = row >> 9;
  const int b  = bh / HH;
  const int kb = mix ? mix[b] : b;
  float* sr = S + (size_t)row*LL;
  const float* mr = amask + (size_t)kb*LL;
  __shared__ float red[4];
  float vals[4], ms[4];
  float mx = -INFINITY;
  #pragma unroll
  for (int r=0;r<4;r++){
    int j = threadIdx.x + 128*r;
    float m = mr[j];
    float v = sr[j]*m;
    vals[r]=v; ms[r]=m;
    mx = fmaxf(mx, v);
  }
  mx = blockMax<4>(mx, red);
  float s = 0.f;
  #pragma unroll
  for (int r=0;r<4;r++){
    float e = expf(vals[r]-mx)*ms[r];
    vals[r] = e; s += e;
  }
  s = blockSum<4>(s, red);
  if (s == 0.f) s = 1.f;
  float inv = 1.f/s;
  #pragma unroll
  for (int r=0;r<4;r++) sr[threadIdx.x + 128*r] = vals[r]*inv;
}

// ---------------- O = softmax(S) @ V ----------------
__global__ void __launch_bounds__(256) attn_av(const float* __restrict__ S,
    const float* __restrict__ v, float* __restrict__ o){
  const int bh = blockIdx.y, b = bh/HH, h = bh%HH;
  const int i0 = blockIdx.x*64;
  __shared__ float Ss[16][68], Vs[16][68];
  const int tid=threadIdx.x, tr=tid>>4, tc=tid&15;
  float acc[4][4]={};
  const float* sbase = S + (size_t)bh*LL*LL;
  for (int j0=0;j0<LL;j0+=16){
    #pragma unroll
    for (int r=0;r<4;r++){
      int idx = tid + 256*r;
      int il = idx>>4, jj = idx&15;
      Ss[jj][il] = sbase[(size_t)(i0+il)*LL + j0+jj];
      int j2 = idx>>6, dl = idx&63;
      Vs[j2][dl] = v[(size_t)(b*LL + j0+j2)*DD + h*KDIM + dl];
    }
    __syncthreads();
    #pragma unroll
    for (int kk=0;kk<16;kk++){
      float4 a = *(const float4*)&Ss[kk][tr*4];
      float4 b4 = *(const float4*)&Vs[kk][tc*4];
      acc[0][0] += a.x*b4.x; acc[0][1] += a.x*b4.y; acc[0][2] += a.x*b4.z; acc[0][3] += a.x*b4.w;
      acc[1][0] += a.y*b4.x; acc[1][1] += a.y*b4.y; acc[1][2] += a.y*b4.z; acc[1][3] += a.y*b4.w;
      acc[2][0] += a.z*b4.x; acc[2][1] += a.z*b4.y; acc[2][2] += a.z*b4.z; acc[2][3] += a.z*b4.w;
      acc[3][0] += a.w*b4.x; acc[3][1] += a.w*b4.y; acc[3][2] += a.w*b4.z; acc[3][3] += a.w*b4.w;
    }
    __syncthreads();
  }
  #pragma unroll
  for (int r=0;r<4;r++){
    int i = i0 + tr*4 + r;
    #pragma unroll
    for (int c=0;c<4;c++){
      int d = tc*4 + c;
      o[(size_t)(b*LL + i)*DD + h*KDIM + d] = acc[r][c];
    }
  }
}

// ---------------- cross-sim argmax ----------------
__global__ void __launch_bounds__(256) cross_argmax(const float* __restrict__ S,
    int* __restrict__ pos){
  const int i = blockIdx.x, b = blockIdx.y;
  if (i == 0 || i == LL-1){
    if (threadIdx.x == 0) pos[b*LL + i] = i;
    return;
  }
  __shared__ float sval[256];
  __shared__ int   sidx[256];
  float best = -1.f; int bestj = 0;
  for (int j = threadIdx.x; j < LL; j += 256){
    if (j < 1 || j > LL-2) continue;
    float cs = -INFINITY;
    #pragma unroll
    for (int h=0; h<HH; h++)
      cs = fmaxf(cs, S[((size_t)(b*HH+h)*LL + i)*LL + j]);
    if (cs > best || (cs == best && j > bestj)){ best = cs; bestj = j; }
  }
  sval[threadIdx.x]=best; sidx[threadIdx.x]=bestj;
  __syncthreads();
  for (int s=128; s; s>>=1){
    if (threadIdx.x < s){
      float v2 = sval[threadIdx.x+s]; int j2 = sidx[threadIdx.x+s];
      if (v2 > sval[threadIdx.x] || (v2 == sval[threadIdx.x] && j2 > sidx[threadIdx.x])){
        sval[threadIdx.x]=v2; sidx[threadIdx.x]=j2;
      }
    }
    __syncthreads();
  }
  if (threadIdx.x == 0) pos[b*LL + i] = sidx[0];
}

// ---------------- mixup apply ----------------
__global__ void __launch_bounds__(256) mixup_apply(const float* __restrict__ h,
    const int* __restrict__ mix, const int* __restrict__ pos,
    const float* __restrict__ alphap, float* __restrict__ outh){
  const int t = blockIdx.x, b = t / LL;
  const float a = *alphap;
  const int mb = mix[b], p = pos[t];
  const float* cur = h + (size_t)t*DD;
  const float* src = h + (size_t)(mb*LL + p)*DD;
  float* dst = outh + (size_t)t*DD;
  for (int d = threadIdx.x; d < DD; d += 256)
    dst[d] = a*cur[d] + (1.f-a)*src[d];
}

__global__ void copyf(const float* __restrict__ s, float* __restrict__ d, int n){
  int i = blockIdx.x*blockDim.x + threadIdx.x;
  if (i < n) d[i] = s[i];
}

// ---------------- embedding + LN ----------------
__global__ void __launch_bounds__(256) embed_ln(const int* __restrict__ ids,
    const float* __restrict__ we, const float* __restrict__ pe, const float* __restrict__ te,
    const float* __restrict__ w, const float* __restrict__ bprm, float* __restrict__ h){
  const int t = blockIdx.x, l = t % LL;
  __shared__ float red[8];
  const int id = ids[t];
  float xs[3]; float s = 0.f;
  #pragma unroll
  for (int r=0;r<3;r++){
    int d = threadIdx.x + 256*r;
    float x = we[(size_t)id*DD + d] + pe[(size_t)l*DD + d] + te[d];
    xs[r]=x; s += x;
  }
  float mu = blockSum<8>(s, red) * (1.f/DD);
  float vs = 0.f;
  #pragma unroll
  for (int r=0;r<3;r++){ float c = xs[r]-mu; vs += c*c; }
  float var = blockSum<8>(vs, red) * (1.f/DD);
  float rstd = rsqrtf(var + 1e-12f);
  #pragma unroll
  for (int r=0;r<3;r++){
    int d = threadIdx.x + 256*r;
    h[(size_t)t*DD + d] = (xs[r]-mu)*rstd*w[d] + bprm[d];
  }
}

// ---------------- h = LN(hin + res) ----------------
__global__ void __launch_bounds__(256) add_ln(const float* __restrict__ hin,
    const float* __restrict__ res, const float* __restrict__ w,
    const float* __restrict__ bprm, float* __restrict__ hout){
  const int t = blockIdx.x;
  __shared__ float red[8];
  float xs[3]; float s = 0.f;
  #pragma unroll
  for (int r=0;r<3;r++){
    int d = threadIdx.x + 256*r;
    float x = hin[(size_t)t*DD + d] + res[(size_t)t*DD + d];
    xs[r]=x; s += x;
  }
  float mu = blockSum<8>(s, red) * (1.f/DD);
  float vs = 0.f;
  #pragma unroll
  for (int r=0;r<3;r++){ float c = xs[r]-mu; vs += c*c; }
  float var = blockSum<8>(vs, red) * (1.f/DD);
  float rstd = rsqrtf(var + 1e-12f);
  #pragma unroll
  for (int r=0;r<3;r++){
    int d = threadIdx.x + 256*r;
    hout[(size_t)t*DD + d] = (xs[r]-mu)*rstd*w[d] + bprm[d];
  }
}

// ---------------- mean pool ----------------
__global__ void __launch_bounds__(256) pool_mean(const float* __restrict__ h,
    float* __restrict__ p){
  const int b = blockIdx.x;
  float acc[3] = {0.f,0.f,0.f};
  for (int l=0; l<LL; l++){
    const float* row = h + (size_t)(b*LL + l)*DD;
    #pragma unroll
    for (int r=0;r<3;r++) acc[r] += row[threadIdx.x + 256*r];
  }
  #pragma unroll
  for (int r=0;r<3;r++)
    p[(size_t)b*DD + threadIdx.x + 256*r] = acc[r]*(1.f/LL);
}

// ---------------- classifier head ----------------
__global__ void __launch_bounds__(128) head_kernel(const float* __restrict__ p,
    const float* __restrict__ c1w, const float* __restrict__ c1b,
    const float* __restrict__ c2w, const float* __restrict__ c2b,
    float* __restrict__ out){
  const int b = blockIdx.x;
  __shared__ float ps[DD];
  __shared__ float c1s[128];
  for (int d = threadIdx.x; d < DD; d += 128) ps[d] = p[(size_t)b*DD + d];
  __syncthreads();
  const int t = threadIdx.x;
  float s = c1b[t];
  for (int d = 0; d < DD; d++) s += ps[d]*c1w[(size_t)d*128 + t];
  c1s[t] = tanhf(s);
  __syncthreads();
  if (t < NCLS){
    float o = c2b[t];
    #pragma unroll
    for (int j=0;j<128;j++) o += c1s[j]*c2w[j*NCLS + t];
    out[b*NCLS + t] = o;
  }
}

// ---------------- launcher ----------------
static void launch_gemm(int act, const float* A, const float* W, const float* bias,
                        float* C, int M, int N, int K){
  dim3 grid(N/128, M/128);
  if (act == 1){
    static int set1 = 0;
    if (!set1){ cudaFuncSetAttribute(gemm_f16x3<1>, cudaFuncAttributeMaxDynamicSharedMemorySize, GEMM_SMEM); set1 = 1; }
    gemm_f16x3<1><<<grid, 256, GEMM_SMEM>>>(A, W, bias, C, M, N, K);
  } else {
    static int set0 = 0;
    if (!set0){ cudaFuncSetAttribute(gemm_f16x3<0>, cudaFuncAttributeMaxDynamicSharedMemorySize, GEMM_SMEM); set0 = 1; }
    gemm_f16x3<0><<<grid, 256, GEMM_SMEM>>>(A, W, bias, C, M, N, K);
  }
}

extern "C" void kernel_launch(void* const* d_in, const int* in_sizes, int n_in,
                              void* d_out, int out_size){
  const int*   ids   = (const int*)  d_in[0];
  const float* amask = (const float*)d_in[1];
  const int*   mix   = (const int*)  d_in[2];
  const float* alpha = (const float*)d_in[6];
  const float* we    = (const float*)d_in[7];
  const float* pe    = (const float*)d_in[8];
  const float* te    = (const float*)d_in[9];
  const float* elnw  = (const float*)d_in[10];
  const float* elnb  = (const float*)d_in[11];
  const float* Wq = (const float*)d_in[12]; const float* bq = (const float*)d_in[13];
  const float* Wk = (const float*)d_in[14]; const float* bk = (const float*)d_in[15];
  const float* Wv = (const float*)d_in[16]; const float* bv = (const float*)d_in[17];
  const float* Wo = (const float*)d_in[18]; const float* bo = (const float*)d_in[19];
  const float* l1w = (const float*)d_in[20]; const float* l1b = (const float*)d_in[21];
  const float* Wf1 = (const float*)d_in[22]; const float* bf1 = (const float*)d_in[23];
  const float* Wf2 = (const float*)d_in[24]; const float* bf2 = (const float*)d_in[25];
  const float* l2w = (const float*)d_in[26]; const float* l2b = (const float*)d_in[27];
  const float* c1w = (const float*)d_in[28]; const float* c1b = (const float*)d_in[29];
  const float* c2w = (const float*)d_in[30]; const float* c2b = (const float*)d_in[31];
  float* out = (float*)d_out;

  float *h,*q,*k,*v,*o,*t1,*t2,*sc,*pl; int* mpos;
  cudaGetSymbolAddress((void**)&h,    g_h);
  cudaGetSymbolAddress((void**)&q,    g_q);
  cudaGetSymbolAddress((void**)&k,    g_k);
  cudaGetSymbolAddress((void**)&v,    g_v);
  cudaGetSymbolAddress((void**)&o,    g_o);
  cudaGetSymbolAddress((void**)&t1,   g_t1);
  cudaGetSymbolAddress((void**)&t2,   g_t2);
  cudaGetSymbolAddress((void**)&sc,   g_scores);
  cudaGetSymbolAddress((void**)&pl,   g_pooled);
  cudaGetSymbolAddress((void**)&mpos, g_mixpos);

  embed_ln<<<NTOK,256>>>(ids, we, pe, te, elnw, elnb, h);

  for (int layer = 0; layer < NLAY; layer++){
    const float* Wq_l = Wq + (size_t)layer*DD*DD;  const float* bq_l = bq + (size_t)layer*DD;
    const float* Wk_l = Wk + (size_t)layer*DD*DD;  const float* bk_l = bk + (size_t)layer*DD;
    const float* Wv_l = Wv + (size_t)layer*DD*DD;  const float* bv_l = bv + (size_t)layer*DD;
    const float* Wo_l = Wo + (size_t)layer*DD*DD;  const float* bo_l = bo + (size_t)layer*DD;
    const float* Wf1_l = Wf1 + (size_t)layer*DD*FFD; const float* bf1_l = bf1 + (size_t)layer*FFD;
    const float* Wf2_l = Wf2 + (size_t)layer*FFD*DD; const float* bf2_l = bf2 + (size_t)layer*DD;

    if (layer == 0){
      launch_gemm(0, h, Wq_l, bq_l, q, NTOK, DD, DD);
      launch_gemm(0, h, Wk_l, bk_l, k, NTOK, DD, DD);
      attn_scores<<<dim3(LL/64, LL/64, BB*HH), 256>>>(q, k, mix, sc);
      softmax512<<<BB*HH*LL, 128>>>(sc, amask, mix);
      cross_argmax<<<dim3(LL, BB), 256>>>(sc, mpos);
      mixup_apply<<<NTOK, 256>>>(h, mix, mpos, alpha, t2);
      copyf<<<(NTOK*DD + 255)/256, 256>>>(t2, h, NTOK*DD);
    }

    launch_gemm(0, h, Wq_l, bq_l, q, NTOK, DD, DD);
    launch_gemm(0, h, Wk_l, bk_l, k, NTOK, DD, DD);
    launch_gemm(0, h, Wv_l, bv_l, v, NTOK, DD, DD);

    attn_scores<<<dim3(LL/64, LL/64, BB*HH), 256>>>(q, k, nullptr, sc);
    softmax512<<<BB*HH*LL, 128>>>(sc, amask, nullptr);
    attn_av<<<dim3(LL/64, BB*HH), 256>>>(sc, v, o);

    launch_gemm(0, o, Wo_l, bo_l, t2, NTOK, DD, DD);
    add_ln<<<NTOK, 256>>>(h, t2, l1w + (size_t)layer*DD, l1b + (size_t)layer*DD, h);

    launch_gemm(1, h, Wf1_l, bf1_l, t1, NTOK, FFD, DD);
    launch_gemm(0, t1, Wf2_l, bf2_l, t2, NTOK, DD, FFD);
    add_ln<<<NTOK, 256>>>(h, t2, l2w + (size_t)layer*DD, l2b + (size_t)layer*DD, h);
  }

  pool_mean<<<BB, 256>>>(h, pl);
  head_kernel<<<BB, 128>>>(pl, c1w, c1b, c2w, c2b, out);
}

// round 5
// speedup vs baseline: 2.5431x; 1.1694x over previous
#include <cuda_runtime.h>
#include <cuda_fp16.h>
#include <math.h>
#include <stdint.h>

#define BB   16
#define LL   512
#define DD   768
#define HH   12
#define KDIM 64
#define FFD  3072
#define NLAY 12
#define NCLS 4
#define NTOK (BB*LL)   // 8192

// ---------------- scratch (device globals; no allocation allowed) ----------------
__device__ float g_h [NTOK*DD];
__device__ float g_q [NTOK*DD];
__device__ float g_k [NTOK*DD];
__device__ float g_v [NTOK*DD];
__device__ float g_o [NTOK*DD];
__device__ float g_t1[(size_t)NTOK*FFD];
__device__ float g_t2[NTOK*DD];
__device__ float g_scores[(size_t)BB*HH*LL*LL];   // 201 MB
__device__ int   g_mixpos[NTOK];
__device__ float g_pooled[BB*DD];

// pre-split weight halves (hi + scaled lo)
__device__ __half g_Wqh[NLAY*DD*DD],  g_Wql[NLAY*DD*DD];
__device__ __half g_Wkh[NLAY*DD*DD],  g_Wkl[NLAY*DD*DD];
__device__ __half g_Wvh[NLAY*DD*DD],  g_Wvl[NLAY*DD*DD];
__device__ __half g_Woh[NLAY*DD*DD],  g_Wol[NLAY*DD*DD];
__device__ __half g_Wf1h[(size_t)NLAY*DD*FFD], g_Wf1l[(size_t)NLAY*DD*FFD];
__device__ __half g_Wf2h[(size_t)NLAY*DD*FFD], g_Wf2l[(size_t)NLAY*DD*FFD];

__device__ __forceinline__ uint32_t smem_u32(const void* p){
  uint32_t a;
  asm("{ .reg .u64 t; cvta.to.shared.u64 t, %1; cvt.u32.u64 %0, t; }" : "=r"(a) : "l"(p));
  return a;
}
__device__ __forceinline__ void mma_f16(float* d, const uint32_t* a, const uint32_t* b){
  asm volatile(
    "mma.sync.aligned.m16n8k16.row.col.f32.f16.f16.f32 "
    "{%0,%1,%2,%3},{%4,%5,%6,%7},{%8,%9},{%0,%1,%2,%3};"
    : "+f"(d[0]), "+f"(d[1]), "+f"(d[2]), "+f"(d[3])
    : "r"(a[0]), "r"(a[1]), "r"(a[2]), "r"(a[3]), "r"(b[0]), "r"(b[1]));
}
__device__ __forceinline__ void ldmat4(uint32_t* r, uint32_t addr){
  asm volatile("ldmatrix.sync.aligned.m8n8.x4.shared.b16 {%0,%1,%2,%3}, [%4];"
    : "=r"(r[0]), "=r"(r[1]), "=r"(r[2]), "=r"(r[3]) : "r"(addr));
}
__device__ __forceinline__ void ldmat4t(uint32_t* r, uint32_t addr){
  asm volatile("ldmatrix.sync.aligned.m8n8.x4.trans.shared.b16 {%0,%1,%2,%3}, [%4];"
    : "=r"(r[0]), "=r"(r[1]), "=r"(r[2]), "=r"(r[3]) : "r"(addr));
}
__device__ __forceinline__ void split2(float x, __half& h, __half& l){
  h = __float2half_rn(x);
  l = __float2half_rn((x - __half2float(h)) * 4096.0f);
}
#define LOSCL (1.0f/4096.0f)

// ---------------- weight pre-split kernel ----------------
__global__ void __launch_bounds__(256) split_w(const float4* __restrict__ src,
    __half2* __restrict__ hi, __half2* __restrict__ lo, int n4){
  int i = blockIdx.x*256 + threadIdx.x;
  if (i >= n4) return;
  float4 v = src[i];
  __half hx,lx,hy,ly,hz,lz,hw,lw;
  split2(v.x,hx,lx); split2(v.y,hy,ly); split2(v.z,hz,lz); split2(v.w,hw,lw);
  hi[2*i]   = __halves2half2(hx,hy);
  hi[2*i+1] = __halves2half2(hz,hw);
  lo[2*i]   = __halves2half2(lx,ly);
  lo[2*i+1] = __halves2half2(lz,lw);
}

// ======================= fp16 3-term GEMM, pre-split weights =======================
#define AROW 40
#define BROW 136
#define OFF_AH 0
#define OFF_AL (128*AROW)
#define OFF_BH (2*128*AROW)
#define OFF_BL (2*128*AROW + 32*BROW)
#define BUF_H  (2*128*AROW + 2*32*BROW)
#define GEMM_SMEM (2*BUF_H*2)

template<int ACT>
__global__ void __launch_bounds__(256) gemm_f16x3(const float* __restrict__ A,
    const __half* __restrict__ Wh, const __half* __restrict__ Wl,
    const float* __restrict__ bias, float* __restrict__ C, int M, int N, int K){
  extern __shared__ __half smh[];
  const uint32_t smb = smem_u32(smh);
  const int tid = threadIdx.x, lane = tid & 31, wid = tid >> 5;
  const int wm = wid & 1, wn = wid >> 1;
  const int g = lane >> 2, tig = lane & 3;
  const int m0 = blockIdx.y * 128, n0 = blockIdx.x * 128;

  float acc [4][4][4] = {};
  float acc2[4][4][4] = {};

  const int a_row  = wm*64 + (lane & 7) + ((lane >> 3) & 1) * 8;
  const int a_koff = (lane & 16) ? 8 : 0;
  const int b_row  = (lane & 7) + ((lane >> 3) & 1) * 8;
  const int b_noff = wn*32 + ((lane & 16) ? 8 : 0);

  // stage tile 0
  #pragma unroll
  for (int i = 0; i < 4; i++){
    int idx = tid + 256*i;
    int r = idx >> 3, kc = (idx & 7) * 4;
    float4 v = *(const float4*)&A[(size_t)(m0 + r)*K + kc];
    __half hx,lx,hy,ly,hz,lz,hw,lw;
    split2(v.x,hx,lx); split2(v.y,hy,ly); split2(v.z,hz,lz); split2(v.w,hw,lw);
    int hb = r*AROW + kc;
    *(__half2*)&smh[OFF_AH + hb]     = __halves2half2(hx,hy);
    *(__half2*)&smh[OFF_AH + hb + 2] = __halves2half2(hz,hw);
    *(__half2*)&smh[OFF_AL + hb]     = __halves2half2(lx,ly);
    *(__half2*)&smh[OFF_AL + hb + 2] = __halves2half2(lz,lw);
  }
  #pragma unroll
  for (int i = 0; i < 2; i++){
    int idx = tid + 256*i;
    int row = idx >> 4, nc = (idx & 15) * 8;
    *(uint4*)&smh[OFF_BH + row*BROW + nc] = *(const uint4*)&Wh[(size_t)row*N + n0 + nc];
    *(uint4*)&smh[OFF_BL + row*BROW + nc] = *(const uint4*)&Wl[(size_t)row*N + n0 + nc];
  }
  __syncthreads();

  const int nkt = K >> 5;
  for (int kt = 0; kt < nkt; kt++){
    float4 rA[4]; uint4 rBh[2], rBl[2];
    const bool pf = (kt + 1 < nkt);
    if (pf){
      int k0 = (kt + 1) << 5;
      #pragma unroll
      for (int i = 0; i < 4; i++){
        int idx = tid + 256*i;
        rA[i] = *(const float4*)&A[(size_t)(m0 + (idx>>3))*K + k0 + (idx&7)*4];
      }
      #pragma unroll
      for (int i = 0; i < 2; i++){
        int idx = tid + 256*i;
        int row = idx >> 4, nc = (idx & 15) * 8;
        rBh[i] = *(const uint4*)&Wh[(size_t)(k0+row)*N + n0 + nc];
        rBl[i] = *(const uint4*)&Wl[(size_t)(k0+row)*N + n0 + nc];
      }
    }
    const uint32_t bufb = smb + (uint32_t)(kt & 1) * (BUF_H * 2);

    #pragma unroll
    for (int ks = 0; ks < 2; ks++){
      uint32_t ah[4][4], al[4][4], bh[4][2], bl[4][2];
      #pragma unroll
      for (int mt = 0; mt < 4; mt++){
        uint32_t ad = bufb + (uint32_t)((a_row + mt*16)*AROW + ks*16 + a_koff) * 2;
        ldmat4(ah[mt], ad + OFF_AH*2);
        ldmat4(al[mt], ad + OFF_AL*2);
      }
      #pragma unroll
      for (int ntp = 0; ntp < 2; ntp++){
        uint32_t bd = bufb + (uint32_t)((b_row + ks*16)*BROW + b_noff + ntp*16) * 2;
        uint32_t th[4], tl[4];
        ldmat4t(th, bd + OFF_BH*2);
        ldmat4t(tl, bd + OFF_BL*2);
        bh[ntp*2][0]=th[0]; bh[ntp*2][1]=th[1]; bh[ntp*2+1][0]=th[2]; bh[ntp*2+1][1]=th[3];
        bl[ntp*2][0]=tl[0]; bl[ntp*2][1]=tl[1]; bl[ntp*2+1][0]=tl[2]; bl[ntp*2+1][1]=tl[3];
      }
      #pragma unroll
      for (int mt = 0; mt < 4; mt++)
        #pragma unroll
        for (int nt = 0; nt < 4; nt++){
          mma_f16(acc [mt][nt], ah[mt], bh[nt]);
          mma_f16(acc2[mt][nt], al[mt], bh[nt]);
          mma_f16(acc2[mt][nt], ah[mt], bl[nt]);
        }
    }

    if (pf){
      __half* dst = smh + ((kt + 1) & 1) * BUF_H;
      #pragma unroll
      for (int i = 0; i < 4; i++){
        int idx = tid + 256*i;
        int r = idx >> 3, kc = (idx & 7) * 4;
        __half hx,lx,hy,ly,hz,lz,hw,lw;
        split2(rA[i].x,hx,lx); split2(rA[i].y,hy,ly); split2(rA[i].z,hz,lz); split2(rA[i].w,hw,lw);
        int hb = r*AROW + kc;
        *(__half2*)&dst[OFF_AH + hb]     = __halves2half2(hx,hy);
        *(__half2*)&dst[OFF_AH + hb + 2] = __halves2half2(hz,hw);
        *(__half2*)&dst[OFF_AL + hb]     = __halves2half2(lx,ly);
        *(__half2*)&dst[OFF_AL + hb + 2] = __halves2half2(lz,lw);
      }
      #pragma unroll
      for (int i = 0; i < 2; i++){
        int idx = tid + 256*i;
        int row = idx >> 4, nc = (idx & 15) * 8;
        *(uint4*)&dst[OFF_BH + row*BROW + nc] = rBh[i];
        *(uint4*)&dst[OFF_BL + row*BROW + nc] = rBl[i];
      }
    }
    __syncthreads();
  }

  #pragma unroll
  for (int mt = 0; mt < 4; mt++){
    int r0 = m0 + wm*64 + mt*16 + g;
    #pragma unroll
    for (int nt = 0; nt < 4; nt++){
      int c = n0 + wn*32 + nt*8 + tig*2;
      float b0 = bias[c], b1 = bias[c+1];
      float2 v0, v1;
      v0.x = acc[mt][nt][0] + LOSCL*acc2[mt][nt][0] + b0;
      v0.y = acc[mt][nt][1] + LOSCL*acc2[mt][nt][1] + b1;
      v1.x = acc[mt][nt][2] + LOSCL*acc2[mt][nt][2] + b0;
      v1.y = acc[mt][nt][3] + LOSCL*acc2[mt][nt][3] + b1;
      if (ACT == 1){
        v0.x = 0.5f*v0.x*(1.0f + erff(v0.x*0.70710678118654752440f));
        v0.y = 0.5f*v0.y*(1.0f + erff(v0.y*0.70710678118654752440f));
        v1.x = 0.5f*v1.x*(1.0f + erff(v1.x*0.70710678118654752440f));
        v1.y = 0.5f*v1.y*(1.0f + erff(v1.y*0.70710678118654752440f));
      }
      *(float2*)&C[(size_t)r0*N + c]     = v0;
      *(float2*)&C[(size_t)(r0+8)*N + c] = v1;
    }
  }
}

// ======================= attention scores via mma (3-term fp16) =======================
// S[b,h,i,j] = 0.125 * q[b,i,h,:]·k[kb,j,h,:].  CTA: 128 i x 128 j, K=64 single stage.
// A = q rows [i][kd]; B staged transposed [kd][j] for the ldmat4t path.
#define S_AROW 72
#define S_BROW 136
#define S_OFF_AH 0
#define S_OFF_AL (128*S_AROW)                  // 9216
#define S_OFF_BH (2*128*S_AROW)                // 18432
#define S_OFF_BL (2*128*S_AROW + 64*S_BROW)    // 27136
#define S_SMEM ((2*128*S_AROW + 2*64*S_BROW)*2) // 71680 bytes

__global__ void __launch_bounds__(256) attn_scores_mma(const float* __restrict__ q,
    const float* __restrict__ k, const int* __restrict__ mix, float* __restrict__ S){
  extern __shared__ __half smh[];
  const uint32_t smb = smem_u32(smh);
  const int bh = blockIdx.z, b = bh / HH, h = bh % HH;
  const int kb = mix ? mix[b] : b;
  const int i0 = blockIdx.y*128, j0 = blockIdx.x*128;
  const int tid = threadIdx.x, lane = tid & 31, wid = tid >> 5;
  const int wm = wid & 1, wn = wid >> 1;
  const int g = lane >> 2, tig = lane & 3;

  // stage A = q (rows i, 64 kd contiguous)
  #pragma unroll
  for (int it = 0; it < 8; it++){
    int idx = tid + 256*it;                 // 2048 float4 = 128x64
    int r = idx >> 4, c = (idx & 15) * 4;
    float4 v = *(const float4*)&q[(size_t)(b*LL + i0 + r)*DD + h*KDIM + c];
    __half hx,lx,hy,ly,hz,lz,hw,lw;
    split2(v.x,hx,lx); split2(v.y,hy,ly); split2(v.z,hz,lz); split2(v.w,hw,lw);
    int hb = r*S_AROW + c;
    *(__half2*)&smh[S_OFF_AH + hb]     = __halves2half2(hx,hy);
    *(__half2*)&smh[S_OFF_AH + hb + 2] = __halves2half2(hz,hw);
    *(__half2*)&smh[S_OFF_AL + hb]     = __halves2half2(lx,ly);
    *(__half2*)&smh[S_OFF_AL + hb + 2] = __halves2half2(lz,lw);
  }
  // stage B = k rows, transposed into [kd][j]
  #pragma unroll
  for (int it = 0; it < 8; it++){
    int idx = tid + 256*it;
    int r = idx >> 4, c = (idx & 15) * 4;   // r = j-local, c = kd
    float4 v = *(const float4*)&k[(size_t)(kb*LL + j0 + r)*DD + h*KDIM + c];
    __half hx,lx,hy,ly,hz,lz,hw,lw;
    split2(v.x,hx,lx); split2(v.y,hy,ly); split2(v.z,hz,lz); split2(v.w,hw,lw);
    smh[S_OFF_BH + (c+0)*S_BROW + r] = hx;
    smh[S_OFF_BH + (c+1)*S_BROW + r] = hy;
    smh[S_OFF_BH + (c+2)*S_BROW + r] = hz;
    smh[S_OFF_BH + (c+3)*S_BROW + r] = hw;
    smh[S_OFF_BL + (c+0)*S_BROW + r] = lx;
    smh[S_OFF_BL + (c+1)*S_BROW + r] = ly;
    smh[S_OFF_BL + (c+2)*S_BROW + r] = lz;
    smh[S_OFF_BL + (c+3)*S_BROW + r] = lw;
  }
  __syncthreads();

  float acc [4][4][4] = {};
  float acc2[4][4][4] = {};
  const int a_row  = wm*64 + (lane & 7) + ((lane >> 3) & 1) * 8;
  const int a_koff = (lane & 16) ? 8 : 0;
  const int b_row  = (lane & 7) + ((lane >> 3) & 1) * 8;
  const int b_noff = wn*32 + ((lane & 16) ? 8 : 0);

  #pragma unroll
  for (int ks = 0; ks < 4; ks++){
    uint32_t ah[4][4], al[4][4], bh[4][2], bl[4][2];
    #pragma unroll
    for (int mt = 0; mt < 4; mt++){
      uint32_t ad = smb + (uint32_t)((a_row + mt*16)*S_AROW + ks*16 + a_koff) * 2;
      ldmat4(ah[mt], ad + S_OFF_AH*2);
      ldmat4(al[mt], ad + S_OFF_AL*2);
    }
    #pragma unroll
    for (int ntp = 0; ntp < 2; ntp++){
      uint32_t bd = smb + (uint32_t)((b_row + ks*16)*S_BROW + b_noff + ntp*16) * 2;
      uint32_t th[4], tl[4];
      ldmat4t(th, bd + S_OFF_BH*2);
      ldmat4t(tl, bd + S_OFF_BL*2);
      bh[ntp*2][0]=th[0]; bh[ntp*2][1]=th[1]; bh[ntp*2+1][0]=th[2]; bh[ntp*2+1][1]=th[3];
      bl[ntp*2][0]=tl[0]; bl[ntp*2][1]=tl[1]; bl[ntp*2+1][0]=tl[2]; bl[ntp*2+1][1]=tl[3];
    }
    #pragma unroll
    for (int mt = 0; mt < 4; mt++)
      #pragma unroll
      for (int nt = 0; nt < 4; nt++){
        mma_f16(acc [mt][nt], ah[mt], bh[nt]);
        mma_f16(acc2[mt][nt], al[mt], bh[nt]);
        mma_f16(acc2[mt][nt], ah[mt], bl[nt]);
      }
  }

  float* sbase = S + (size_t)bh*LL*LL;
  #pragma unroll
  for (int mt = 0; mt < 4; mt++){
    int r0 = i0 + wm*64 + mt*16 + g;
    #pragma unroll
    for (int nt = 0; nt < 4; nt++){
      int c = j0 + wn*32 + nt*8 + tig*2;
      float2 v0, v1;
      v0.x = (acc[mt][nt][0] + LOSCL*acc2[mt][nt][0]) * 0.125f;
      v0.y = (acc[mt][nt][1] + LOSCL*acc2[mt][nt][1]) * 0.125f;
      v1.x = (acc[mt][nt][2] + LOSCL*acc2[mt][nt][2]) * 0.125f;
      v1.y = (acc[mt][nt][3] + LOSCL*acc2[mt][nt][3]) * 0.125f;
      *(float2*)&sbase[(size_t)r0*LL + c]     = v0;
      *(float2*)&sbase[(size_t)(r0+8)*LL + c] = v1;
    }
  }
}

// ======================= O = softmax(S) @ V via mma (3-term fp16) =======================
// Per (b,h): M=512 i, N=64 d, K=512 j.  CTA 128x64, BK=32 double-buffered.
#define V_AROW 40
#define V_BROW 72
#define V_OFF_AH 0
#define V_OFF_AL (128*V_AROW)               // 5120
#define V_OFF_BH (2*128*V_AROW)             // 10240
#define V_OFF_BL (2*128*V_AROW + 32*V_BROW) // 12544
#define V_BUF_H  (2*128*V_AROW + 2*32*V_BROW) // 14848
#define V_SMEM (2*V_BUF_H*2)                  // 59392 bytes

__global__ void __launch_bounds__(256) attn_av_mma(const float* __restrict__ S,
    const float* __restrict__ v, float* __restrict__ o){
  extern __shared__ __half smh[];
  const uint32_t smb = smem_u32(smh);
  const int bh = blockIdx.y, b = bh / HH, h = bh % HH;
  const int i0 = blockIdx.x*128;
  const int tid = threadIdx.x, lane = tid & 31, wid = tid >> 5;
  const int wm = wid & 3, wn = wid >> 2;
  const int g = lane >> 2, tig = lane & 3;
  const float* sbase = S + (size_t)bh*LL*LL;

  float acc [2][4][4] = {};
  float acc2[2][4][4] = {};
  const int a_row  = wm*32 + (lane & 7) + ((lane >> 3) & 1) * 8;
  const int a_koff = (lane & 16) ? 8 : 0;
  const int b_row  = (lane & 7) + ((lane >> 3) & 1) * 8;
  const int b_noff = wn*32 + ((lane & 16) ? 8 : 0);

  // stage tile 0
  #pragma unroll
  for (int i = 0; i < 4; i++){
    int idx = tid + 256*i;                 // 1024 float4 = 128x32
    int r = idx >> 3, c = (idx & 7) * 4;
    float4 w = *(const float4*)&sbase[(size_t)(i0 + r)*LL + c];
    __half hx,lx,hy,ly,hz,lz,hw,lw;
    split2(w.x,hx,lx); split2(w.y,hy,ly); split2(w.z,hz,lz); split2(w.w,hw,lw);
    int hb = r*V_AROW + c;
    *(__half2*)&smh[V_OFF_AH + hb]     = __halves2half2(hx,hy);
    *(__half2*)&smh[V_OFF_AH + hb + 2] = __halves2half2(hz,hw);
    *(__half2*)&smh[V_OFF_AL + hb]     = __halves2half2(lx,ly);
    *(__half2*)&smh[V_OFF_AL + hb + 2] = __halves2half2(lz,lw);
  }
  #pragma unroll
  for (int i = 0; i < 2; i++){
    int idx = tid + 256*i;                 // 512 float4 = 32x64
    int r = idx >> 4, c = (idx & 15) * 4;
    float4 w = *(const float4*)&v[(size_t)(b*LL + r)*DD + h*KDIM + c];
    __half hx,lx,hy,ly,hz,lz,hw,lw;
    split2(w.x,hx,lx); split2(w.y,hy,ly); split2(w.z,hz,lz); split2(w.w,hw,lw);
    int hb = r*V_BROW + c;
    *(__half2*)&smh[V_OFF_BH + hb]     = __halves2half2(hx,hy);
    *(__half2*)&smh[V_OFF_BH + hb + 2] = __halves2half2(hz,hw);
    *(__half2*)&smh[V_OFF_BL + hb]     = __halves2half2(lx,ly);
    *(__half2*)&smh[V_OFF_BL + hb + 2] = __halves2half2(lz,lw);
  }
  __syncthreads();

  for (int kt = 0; kt < 16; kt++){
    float4 rA[4], rB[2];
    const bool pf = (kt + 1 < 16);
    if (pf){
      int k0 = (kt + 1) << 5;
      #pragma unroll
      for (int i = 0; i < 4; i++){
        int idx = tid + 256*i;
        rA[i] = *(const float4*)&sbase[(size_t)(i0 + (idx>>3))*LL + k0 + (idx&7)*4];
      }
      #pragma unroll
      for (int i = 0; i < 2; i++){
        int idx = tid + 256*i;
        rB[i] = *(const float4*)&v[(size_t)(b*LL + k0 + (idx>>4))*DD + h*KDIM + (idx&15)*4];
      }
    }
    const uint32_t bufb = smb + (uint32_t)(kt & 1) * (V_BUF_H * 2);

    #pragma unroll
    for (int ks = 0; ks < 2; ks++){
      uint32_t ah[2][4], al[2][4], bh[4][2], bl[4][2];
      #pragma unroll
      for (int mt = 0; mt < 2; mt++){
        uint32_t ad = bufb + (uint32_t)((a_row + mt*16)*V_AROW + ks*16 + a_koff) * 2;
        ldmat4(ah[mt], ad + V_OFF_AH*2);
        ldmat4(al[mt], ad + V_OFF_AL*2);
      }
      #pragma unroll
      for (int ntp = 0; ntp < 2; ntp++){
        uint32_t bd = bufb + (uint32_t)((b_row + ks*16)*V_BROW + b_noff + ntp*16) * 2;
        uint32_t th[4], tl[4];
        ldmat4t(th, bd + V_OFF_BH*2);
        ldmat4t(tl, bd + V_OFF_BL*2);
        bh[ntp*2][0]=th[0]; bh[ntp*2][1]=th[1]; bh[ntp*2+1][0]=th[2]; bh[ntp*2+1][1]=th[3];
        bl[ntp*2][0]=tl[0]; bl[ntp*2][1]=tl[1]; bl[ntp*2+1][0]=tl[2]; bl[ntp*2+1][1]=tl[3];
      }
      #pragma unroll
      for (int mt = 0; mt < 2; mt++)
        #pragma unroll
        for (int nt = 0; nt < 4; nt++){
          mma_f16(acc [mt][nt], ah[mt], bh[nt]);
          mma_f16(acc2[mt][nt], al[mt], bh[nt]);
          mma_f16(acc2[mt][nt], ah[mt], bl[nt]);
        }
    }

    if (pf){
      __half* dst = smh + ((kt + 1) & 1) * V_BUF_H;
      #pragma unroll
      for (int i = 0; i < 4; i++){
        int idx = tid + 256*i;
        int r = idx >> 3, c = (idx & 7) * 4;
        __half hx,lx,hy,ly,hz,lz,hw,lw;
        split2(rA[i].x,hx,lx); split2(rA[i].y,hy,ly); split2(rA[i].z,hz,lz); split2(rA[i].w,hw,lw);
        int hb = r*V_AROW + c;
        *(__half2*)&dst[V_OFF_AH + hb]     = __halves2half2(hx,hy);
        *(__half2*)&dst[V_OFF_AH + hb + 2] = __halves2half2(hz,hw);
        *(__half2*)&dst[V_OFF_AL + hb]     = __halves2half2(lx,ly);
        *(__half2*)&dst[V_OFF_AL + hb + 2] = __halves2half2(lz,lw);
      }
      #pragma unroll
      for (int i = 0; i < 2; i++){
        int idx = tid + 256*i;
        int r = idx >> 4, c = (idx & 15) * 4;
        __half hx,lx,hy,ly,hz,lz,hw,lw;
        split2(rB[i].x,hx,lx); split2(rB[i].y,hy,ly); split2(rB[i].z,hz,lz); split2(rB[i].w,hw,lw);
        int hb = r*V_BROW + c;
        *(__half2*)&dst[V_OFF_BH + hb]     = __halves2half2(hx,hy);
        *(__half2*)&dst[V_OFF_BH + hb + 2] = __halves2half2(hz,hw);
        *(__half2*)&dst[V_OFF_BL + hb]     = __halves2half2(lx,ly);
        *(__half2*)&dst[V_OFF_BL + hb + 2] = __halves2half2(lz,lw);
      }
    }
    __syncthreads();
  }

  #pragma unroll
  for (int mt = 0; mt < 2; mt++){
    int r0 = i0 + wm*32 + mt*16 + g;
    #pragma unroll
    for (int nt = 0; nt < 4; nt++){
      int c = wn*32 + nt*8 + tig*2;
      float2 v0, v1;
      v0.x = acc[mt][nt][0] + LOSCL*acc2[mt][nt][0];
      v0.y = acc[mt][nt][1] + LOSCL*acc2[mt][nt][1];
      v1.x = acc[mt][nt][2] + LOSCL*acc2[mt][nt][2];
      v1.y = acc[mt][nt][3] + LOSCL*acc2[mt][nt][3];
      *(float2*)&o[(size_t)(b*LL + r0)*DD + h*KDIM + c]     = v0;
      *(float2*)&o[(size_t)(b*LL + r0 + 8)*DD + h*KDIM + c] = v1;
    }
  }
}

// ---------------- reductions ----------------
__device__ __forceinline__ float warpSum(float v){
  #pragma unroll
  for (int o=16;o;o>>=1) v += __shfl_xor_sync(0xffffffffu, v, o);
  return v;
}
__device__ __forceinline__ float warpMax(float v){
  #pragma unroll
  for (int o=16;o;o>>=1) v = fmaxf(v, __shfl_xor_sync(0xffffffffu, v, o));
  return v;
}
template<int NWARP>
__device__ __forceinline__ float blockSum(float v, float* sh){
  int lane = threadIdx.x & 31, w = threadIdx.x >> 5;
  v = warpSum(v);
  if (lane == 0) sh[w] = v;
  __syncthreads();
  float r = (lane < NWARP) ? sh[lane] : 0.f;
  r = warpSum(r);
  __syncthreads();
  return r;
}
template<int NWARP>
__device__ __forceinline__ float blockMax(float v, float* sh){
  int lane = threadIdx.x & 31, w = threadIdx.x >> 5;
  v = warpMax(v);
  if (lane == 0) sh[w] = v;
  __syncthreads();
  float r = (lane < NWARP) ? sh[lane] : -INFINITY;
  r = warpMax(r);
  __syncthreads();
  return r;
}

// ---------------- masked softmax (exact reference semantics) ----------------
__global__ void __launch_bounds__(128) softmax512(float* __restrict__ S,
    const float* __restrict__ amask, const int* __restrict__ mix){
  const int row = blockIdx.x;
  const int bh = row >> 9;
  const int b  = bh / HH;
  const int kb = mix ? mix[b] : b;
  float* sr = S + (size_t)row*LL;
  const float* mr = amask + (size_t)kb*LL;
  __shared__ float red[4];
  float vals[4], ms[4];
  float mx = -INFINITY;
  #pragma unroll
  for (int r=0;r<4;r++){
    int j = threadIdx.x + 128*r;
    float m = mr[j];
    float v = sr[j]*m;
    vals[r]=v; ms[r]=m;
    mx = fmaxf(mx, v);
  }
  mx = blockMax<4>(mx, red);
  float s = 0.f;
  #pragma unroll
  for (int r=0;r<4;r++){
    float e = expf(vals[r]-mx)*ms[r];
    vals[r] = e; s += e;
  }
  s = blockSum<4>(s, red);
  if (s == 0.f) s = 1.f;
  float inv = 1.f/s;
  #pragma unroll
  for (int r=0;r<4;r++) sr[threadIdx.x + 128*r] = vals[r]*inv;
}

// ---------------- cross-sim argmax ----------------
__global__ void __launch_bounds__(256) cross_argmax(const float* __restrict__ S,
    int* __restrict__ pos){
  const int i = blockIdx.x, b = blockIdx.y;
  if (i == 0 || i == LL-1){
    if (threadIdx.x == 0) pos[b*LL + i] = i;
    return;
  }
  __shared__ float sval[256];
  __shared__ int   sidx[256];
  float best = -1.f; int bestj = 0;
  for (int j = threadIdx.x; j < LL; j += 256){
    if (j < 1 || j > LL-2) continue;
    float cs = -INFINITY;
    #pragma unroll
    for (int h=0; h<HH; h++)
      cs = fmaxf(cs, S[((size_t)(b*HH+h)*LL + i)*LL + j]);
    if (cs > best || (cs == best && j > bestj)){ best = cs; bestj = j; }
  }
  sval[threadIdx.x]=best; sidx[threadIdx.x]=bestj;
  __syncthreads();
  for (int s=128; s; s>>=1){
    if (threadIdx.x < s){
      float v2 = sval[threadIdx.x+s]; int j2 = sidx[threadIdx.x+s];
      if (v2 > sval[threadIdx.x] || (v2 == sval[threadIdx.x] && j2 > sidx[threadIdx.x])){
        sval[threadIdx.x]=v2; sidx[threadIdx.x]=j2;
      }
    }
    __syncthreads();
  }
  if (threadIdx.x == 0) pos[b*LL + i] = sidx[0];
}

// ---------------- mixup apply ----------------
__global__ void __launch_bounds__(256) mixup_apply(const float* __restrict__ h,
    const int* __restrict__ mix, const int* __restrict__ pos,
    const float* __restrict__ alphap, float* __restrict__ outh){
  const int t = blockIdx.x, b = t / LL;
  const float a = *alphap;
  const int mb = mix[b], p = pos[t];
  const float* cur = h + (size_t)t*DD;
  const float* src = h + (size_t)(mb*LL + p)*DD;
  float* dst = outh + (size_t)t*DD;
  for (int d = threadIdx.x; d < DD; d += 256)
    dst[d] = a*cur[d] + (1.f-a)*src[d];
}

__global__ void copyf(const float* __restrict__ s, float* __restrict__ d, int n){
  int i = blockIdx.x*blockDim.x + threadIdx.x;
  if (i < n) d[i] = s[i];
}

// ---------------- embedding + LN ----------------
__global__ void __launch_bounds__(256) embed_ln(const int* __restrict__ ids,
    const float* __restrict__ we, const float* __restrict__ pe, const float* __restrict__ te,
    const float* __restrict__ w, const float* __restrict__ bprm, float* __restrict__ h){
  const int t = blockIdx.x, l = t % LL;
  __shared__ float red[8];
  const int id = ids[t];
  float xs[3]; float s = 0.f;
  #pragma unroll
  for (int r=0;r<3;r++){
    int d = threadIdx.x + 256*r;
    float x = we[(size_t)id*DD + d] + pe[(size_t)l*DD + d] + te[d];
    xs[r]=x; s += x;
  }
  float mu = blockSum<8>(s, red) * (1.f/DD);
  float vs = 0.f;
  #pragma unroll
  for (int r=0;r<3;r++){ float c = xs[r]-mu; vs += c*c; }
  float var = blockSum<8>(vs, red) * (1.f/DD);
  float rstd = rsqrtf(var + 1e-12f);
  #pragma unroll
  for (int r=0;r<3;r++){
    int d = threadIdx.x + 256*r;
    h[(size_t)t*DD + d] = (xs[r]-mu)*rstd*w[d] + bprm[d];
  }
}

// ---------------- h = LN(hin + res) ----------------
__global__ void __launch_bounds__(256) add_ln(const float* __restrict__ hin,
    const float* __restrict__ res, const float* __restrict__ w,
    const float* __restrict__ bprm, float* __restrict__ hout){
  const int t = blockIdx.x;
  __shared__ float red[8];
  float xs[3]; float s = 0.f;
  #pragma unroll
  for (int r=0;r<3;r++){
    int d = threadIdx.x + 256*r;
    float x = hin[(size_t)t*DD + d] + res[(size_t)t*DD + d];
    xs[r]=x; s += x;
  }
  float mu = blockSum<8>(s, red) * (1.f/DD);
  float vs = 0.f;
  #pragma unroll
  for (int r=0;r<3;r++){ float c = xs[r]-mu; vs += c*c; }
  float var = blockSum<8>(vs, red) * (1.f/DD);
  float rstd = rsqrtf(var + 1e-12f);
  #pragma unroll
  for (int r=0;r<3;r++){
    int d = threadIdx.x + 256*r;
    hout[(size_t)t*DD + d] = (xs[r]-mu)*rstd*w[d] + bprm[d];
  }
}

// ---------------- mean pool ----------------
__global__ void __launch_bounds__(256) pool_mean(const float* __restrict__ h,
    float* __restrict__ p){
  const int b = blockIdx.x;
  float acc[3] = {0.f,0.f,0.f};
  for (int l=0; l<LL; l++){
    const float* row = h + (size_t)(b*LL + l)*DD;
    #pragma unroll
    for (int r=0;r<3;r++) acc[r] += row[threadIdx.x + 256*r];
  }
  #pragma unroll
  for (int r=0;r<3;r++)
    p[(size_t)b*DD + threadIdx.x + 256*r] = acc[r]*(1.f/LL);
}

// ---------------- classifier head ----------------
__global__ void __launch_bounds__(128) head_kernel(const float* __restrict__ p,
    const float* __restrict__ c1w, const float* __restrict__ c1b,
    const float* __restrict__ c2w, const float* __restrict__ c2b,
    float* __restrict__ out){
  const int b = blockIdx.x;
  __shared__ float ps[DD];
  __shared__ float c1s[128];
  for (int d = threadIdx.x; d < DD; d += 128) ps[d] = p[(size_t)b*DD + d];
  __syncthreads();
  const int t = threadIdx.x;
  float s = c1b[t];
  for (int d = 0; d < DD; d++) s += ps[d]*c1w[(size_t)d*128 + t];
  c1s[t] = tanhf(s);
  __syncthreads();
  if (t < NCLS){
    float o = c2b[t];
    #pragma unroll
    for (int j=0;j<128;j++) o += c1s[j]*c2w[j*NCLS + t];
    out[b*NCLS + t] = o;
  }
}

// ---------------- launcher ----------------
static void launch_gemm(int act, const float* A, const __half* Wh, const __half* Wl,
                        const float* bias, float* C, int M, int N, int K){
  dim3 grid(N/128, M/128);
  if (act == 1){
    static int s1 = 0;
    if (!s1){ cudaFuncSetAttribute(gemm_f16x3<1>, cudaFuncAttributeMaxDynamicSharedMemorySize, GEMM_SMEM); s1 = 1; }
    gemm_f16x3<1><<<grid, 256, GEMM_SMEM>>>(A, Wh, Wl, bias, C, M, N, K);
  } else {
    static int s0 = 0;
    if (!s0){ cudaFuncSetAttribute(gemm_f16x3<0>, cudaFuncAttributeMaxDynamicSharedMemorySize, GEMM_SMEM); s0 = 1; }
    gemm_f16x3<0><<<grid, 256, GEMM_SMEM>>>(A, Wh, Wl, bias, C, M, N, K);
  }
}

extern "C" void kernel_launch(void* const* d_in, const int* in_sizes, int n_in,
                              void* d_out, int out_size){
  const int*   ids   = (const int*)  d_in[0];
  const float* amask = (const float*)d_in[1];
  const int*   mix   = (const int*)  d_in[2];
  const float* alpha = (const float*)d_in[6];
  const float* we    = (const float*)d_in[7];
  const float* pe    = (const float*)d_in[8];
  const float* te    = (const float*)d_in[9];
  const float* elnw  = (const float*)d_in[10];
  const float* elnb  = (const float*)d_in[11];
  const float* Wq = (const float*)d_in[12]; const float* bq = (const float*)d_in[13];
  const float* Wk = (const float*)d_in[14]; const float* bk = (const float*)d_in[15];
  const float* Wv = (const float*)d_in[16]; const float* bv = (const float*)d_in[17];
  const float* Wo = (const float*)d_in[18]; const float* bo = (const float*)d_in[19];
  const float* l1w = (const float*)d_in[20]; const float* l1b = (const float*)d_in[21];
  const float* Wf1 = (const float*)d_in[22]; const float* bf1 = (const float*)d_in[23];
  const float* Wf2 = (const float*)d_in[24]; const float* bf2 = (const float*)d_in[25];
  const float* l2w = (const float*)d_in[26]; const float* l2b = (const float*)d_in[27];
  const float* c1w = (const float*)d_in[28]; const float* c1b = (const float*)d_in[29];
  const float* c2w = (const float*)d_in[30]; const float* c2b = (const float*)d_in[31];
  float* out = (float*)d_out;

  float *h,*q,*k,*v,*o,*t1,*t2,*sc,*pl; int* mpos;
  cudaGetSymbolAddress((void**)&h,    g_h);
  cudaGetSymbolAddress((void**)&q,    g_q);
  cudaGetSymbolAddress((void**)&k,    g_k);
  cudaGetSymbolAddress((void**)&v,    g_v);
  cudaGetSymbolAddress((void**)&o,    g_o);
  cudaGetSymbolAddress((void**)&t1,   g_t1);
  cudaGetSymbolAddress((void**)&t2,   g_t2);
  cudaGetSymbolAddress((void**)&sc,   g_scores);
  cudaGetSymbolAddress((void**)&pl,   g_pooled);
  cudaGetSymbolAddress((void**)&mpos, g_mixpos);

  __half *Wqh,*Wql,*Wkh,*Wkl,*Wvh,*Wvl,*Woh,*Wol,*Wf1h,*Wf1l,*Wf2h,*Wf2l;
  cudaGetSymbolAddress((void**)&Wqh,  g_Wqh);  cudaGetSymbolAddress((void**)&Wql,  g_Wql);
  cudaGetSymbolAddress((void**)&Wkh,  g_Wkh);  cudaGetSymbolAddress((void**)&Wkl,  g_Wkl);
  cudaGetSymbolAddress((void**)&Wvh,  g_Wvh);  cudaGetSymbolAddress((void**)&Wvl,  g_Wvl);
  cudaGetSymbolAddress((void**)&Woh,  g_Woh);  cudaGetSymbolAddress((void**)&Wol,  g_Wol);
  cudaGetSymbolAddress((void**)&Wf1h, g_Wf1h); cudaGetSymbolAddress((void**)&Wf1l, g_Wf1l);
  cudaGetSymbolAddress((void**)&Wf2h, g_Wf2h); cudaGetSymbolAddress((void**)&Wf2l, g_Wf2l);

  // pre-split all weights
  {
    int n4s = NLAY*DD*DD/4;
    split_w<<<(n4s+255)/256,256>>>((const float4*)Wq, (__half2*)Wqh, (__half2*)Wql, n4s);
    split_w<<<(n4s+255)/256,256>>>((const float4*)Wk, (__half2*)Wkh, (__half2*)Wkl, n4s);
    split_w<<<(n4s+255)/256,256>>>((const float4*)Wv, (__half2*)Wvh, (__half2*)Wvl, n4s);
    split_w<<<(n4s+255)/256,256>>>((const float4*)Wo, (__half2*)Woh, (__half2*)Wol, n4s);
    int n4f = NLAY*DD*FFD/4;
    split_w<<<(n4f+255)/256,256>>>((const float4*)Wf1, (__half2*)Wf1h, (__half2*)Wf1l, n4f);
    split_w<<<(n4f+255)/256,256>>>((const float4*)Wf2, (__half2*)Wf2h, (__half2*)Wf2l, n4f);
  }

  static int attrset = 0;
  if (!attrset){
    cudaFuncSetAttribute(attn_scores_mma, cudaFuncAttributeMaxDynamicSharedMemorySize, S_SMEM);
    cudaFuncSetAttribute(attn_av_mma,     cudaFuncAttributeMaxDynamicSharedMemorySize, V_SMEM);
    attrset = 1;
  }

  embed_ln<<<NTOK,256>>>(ids, we, pe, te, elnw, elnb, h);

  for (int layer = 0; layer < NLAY; layer++){
    const size_t od = (size_t)layer*DD*DD;
    const size_t of = (size_t)layer*DD*FFD;
    const float* bq_l = bq + (size_t)layer*DD;
    const float* bk_l = bk + (size_t)layer*DD;
    const float* bv_l = bv + (size_t)layer*DD;
    const float* bo_l = bo + (size_t)layer*DD;
    const float* bf1_l = bf1 + (size_t)layer*FFD;
    const float* bf2_l = bf2 + (size_t)layer*DD;

    if (layer == 0){
      launch_gemm(0, h, Wqh+od, Wql+od, bq_l, q, NTOK, DD, DD);
      launch_gemm(0, h, Wkh+od, Wkl+od, bk_l, k, NTOK, DD, DD);
      attn_scores_mma<<<dim3(LL/128, LL/128, BB*HH), 256, S_SMEM>>>(q, k, mix, sc);
      softmax512<<<BB*HH*LL, 128>>>(sc, amask, mix);
      cross_argmax<<<dim3(LL, BB), 256>>>(sc, mpos);
      mixup_apply<<<NTOK, 256>>>(h, mix, mpos, alpha, t2);
      copyf<<<(NTOK*DD + 255)/256, 256>>>(t2, h, NTOK*DD);
    }

    launch_gemm(0, h, Wqh+od, Wql+od, bq_l, q, NTOK, DD, DD);
    launch_gemm(0, h, Wkh+od, Wkl+od, bk_l, k, NTOK, DD, DD);
    launch_gemm(0, h, Wvh+od, Wvl+od, bv_l, v, NTOK, DD, DD);

    attn_scores_mma<<<dim3(LL/128, LL/128, BB*HH), 256, S_SMEM>>>(q, k, nullptr, sc);
    softmax512<<<BB*HH*LL, 128>>>(sc, amask, nullptr);
    attn_av_mma<<<dim3(LL/128, BB*HH), 256, V_SMEM>>>(sc, v, o);

    launch_gemm(0, o, Woh+od, Wol+od, bo_l, t2, NTOK, DD, DD);
    add_ln<<<NTOK, 256>>>(h, t2, l1w + (size_t)layer*DD, l1b + (size_t)layer*DD, h);

    launch_gemm(1, h, Wf1h+of, Wf1l+of, bf1_l, t1, NTOK, FFD, DD);
    launch_gemm(0, t1, Wf2h+of, Wf2l+of, bf2_l, t2, NTOK, DD, FFD);
    add_ln<<<NTOK, 256>>>(h, t2, l2w + (size_t)layer*DD, l2b + (size_t)layer*DD, h);
  }

  pool_mean<<<BB, 256>>>(h, pl);
  head_kernel<<<BB, 128>>>(pl, c1w, c1b, c2w, c2b, out);
}